// round 9
// baseline (speedup 1.0000x reference)
#include <cuda_runtime.h>

#define Bsz 256
#define Csz 128
#define Nsz 64
#define Psz 16
#define Qsz 48
#define TB 128
#define WPB 4
#define SWEEPS_W 6
#define SWEEPS_NV 4
#define SWEEPS_D 5
#define SWEEPS_R 6
#define S17 17
#define RTOL 1e-2f

// ---------------- device scratch (static, no allocations) ----------------
__device__ alignas(16) float gXlog[(size_t)Bsz * Csz * Nsz * Psz]; // 128MB
__device__ float gTheta[Bsz * Csz];
__device__ alignas(16) float gBmF[Csz * Qsz * Psz];
__device__ alignas(16) float gGinvCF[Csz * Psz * Psz];
__device__ alignas(16) float gGinvBF[Psz * Psz];
__device__ float gFactorF[Csz];

// ================= warp-level fp32 Jacobi (stride-17 smem) =================
__device__ __forceinline__ void jacobi_warp(float* W, float* V, int lane,
                                            int sweeps, bool wantV) {
    const int j = lane >> 2;
    const int b4 = (lane & 3) * 4;
    for (int sweep = 0; sweep < sweeps; ++sweep) {
        for (int r = 0; r < 15; ++r) {
            int p, q;
            if (j == 0) { p = 15; q = r; }
            else { p = (r + j) % 15; q = (r + 15 - j) % 15; }
            if (p < q) { int tmp = p; p = q; q = tmp; }
            __syncwarp();
            float c = 1.f, s = 0.f;
            if ((lane & 3) == 0) {
                float app = W[p * S17 + p], aqq = W[q * S17 + q], apq = W[p * S17 + q];
                if (fabsf(apq) > 1e-37f) {
                    float tau = (aqq - app) / (2.f * apq);
                    float tt = copysignf(1.f, tau) / (fabsf(tau) + sqrtf(1.f + tau * tau));
                    c = rsqrtf(1.f + tt * tt);
                    s = tt * c;
                }
            }
            c = __shfl_sync(0xffffffffu, c, lane & ~3);
            s = __shfl_sync(0xffffffffu, s, lane & ~3);
            #pragma unroll
            for (int k = 0; k < 4; ++k) {
                int col = b4 + k;
                float wp = W[p * S17 + col], wq = W[q * S17 + col];
                W[p * S17 + col] = c * wp - s * wq;
                W[q * S17 + col] = s * wp + c * wq;
            }
            __syncwarp();
            #pragma unroll
            for (int k = 0; k < 4; ++k) {
                int row = b4 + k;
                float xp = W[row * S17 + p], xq = W[row * S17 + q];
                W[row * S17 + p] = c * xp - s * xq;
                W[row * S17 + q] = s * xp + c * xq;
                if (wantV) {
                    float vp = V[row * S17 + p], vq = V[row * S17 + q];
                    V[row * S17 + p] = c * vp - s * vq;
                    V[row * S17 + q] = s * vp + c * vq;
                }
            }
        }
    }
    __syncwarp();
}

// ================= warp-level fp64 Jacobi (stride-16, rescue path) =================
__device__ void jacobi_warp_d(double* W, double* V, int lane, int sweeps) {
    for (int i = lane; i < 256; i += 32) V[i] = ((i >> 4) == (i & 15)) ? 1.0 : 0.0;
    __syncwarp();
    const int j = lane >> 2;
    const int b4 = (lane & 3) * 4;
    for (int sweep = 0; sweep < sweeps; ++sweep) {
        for (int r = 0; r < 15; ++r) {
            int p, q;
            if (j == 0) { p = 15; q = r; }
            else { p = (r + j) % 15; q = (r + 15 - j) % 15; }
            if (p < q) { int tmp = p; p = q; q = tmp; }
            __syncwarp();
            double c = 1.0, s = 0.0;
            if ((lane & 3) == 0) {
                double app = W[p * 16 + p], aqq = W[q * 16 + q], apq = W[p * 16 + q];
                if (fabs(apq) > 1e-300) {
                    double tau = (aqq - app) / (2.0 * apq);
                    double tt = copysign(1.0, tau) / (fabs(tau) + sqrt(1.0 + tau * tau));
                    c = rsqrt(1.0 + tt * tt);
                    s = tt * c;
                }
            }
            c = __shfl_sync(0xffffffffu, c, lane & ~3);
            s = __shfl_sync(0xffffffffu, s, lane & ~3);
            #pragma unroll
            for (int k = 0; k < 4; ++k) {
                int col = b4 + k;
                double wp = W[p * 16 + col], wq = W[q * 16 + col];
                W[p * 16 + col] = c * wp - s * wq;
                W[q * 16 + col] = s * wp + c * wq;
            }
            __syncwarp();
            #pragma unroll
            for (int k = 0; k < 4; ++k) {
                int row = b4 + k;
                double xp = W[row * 16 + p], xq = W[row * 16 + q];
                W[row * 16 + p] = c * xp - s * xq;
                W[row * 16 + q] = s * xp + c * xq;
                double vp = V[row * 16 + p], vq = V[row * 16 + q];
                V[row * 16 + p] = c * vp - s * vq;
                V[row * 16 + q] = s * vp + c * vq;
            }
            __syncwarp();
        }
    }
    __syncwarp();
}

// ================= block-level fp64 helpers (k2/k4) =================
__device__ void jacobi16d(double* W, double* V, double* cs) {
    const int t = threadIdx.x;
    for (int i = t; i < 256; i += TB) V[i] = ((i >> 4) == (i & 15)) ? 1.0 : 0.0;
    __syncthreads();
    const int pr = t >> 4, el = t & 15;
    for (int sweep = 0; sweep < SWEEPS_D; ++sweep) {
        for (int r = 0; r < 15; ++r) {
            int p, q;
            if (pr == 0) { p = 15; q = r; }
            else { p = (r + pr) % 15; q = (r + 15 - pr) % 15; }
            if (p < q) { int tmp = p; p = q; q = tmp; }
            if (el == 0) {
                double app = W[p * 16 + p], aqq = W[q * 16 + q], apq = W[p * 16 + q];
                double c = 1.0, s = 0.0;
                if (fabs(apq) > 1e-300) {
                    double tau = (aqq - app) / (2.0 * apq);
                    double tt = copysign(1.0, tau) / (fabs(tau) + sqrt(1.0 + tau * tau));
                    c = rsqrt(1.0 + tt * tt);
                    s = tt * c;
                }
                cs[pr] = c; cs[8 + pr] = s;
            }
            __syncthreads();
            double c = cs[pr], s = cs[8 + pr];
            double wp = W[p * 16 + el], wq = W[q * 16 + el];
            W[p * 16 + el] = c * wp - s * wq;
            W[q * 16 + el] = s * wp + c * wq;
            __syncthreads();
            double xp = W[el * 16 + p], xq = W[el * 16 + q];
            W[el * 16 + p] = c * xp - s * xq;
            W[el * 16 + q] = s * xp + c * xq;
            double vp = V[el * 16 + p], vq = V[el * 16 + q];
            V[el * 16 + p] = c * vp - s * vq;
            V[el * 16 + q] = s * vp + c * vq;
            __syncthreads();
        }
    }
}

__device__ void invert16d(const double* Min, double* aug, double* Mout, double* fs, int* piv) {
    const int t = threadIdx.x;
    for (int i = t; i < 512; i += TB) {
        int r = i >> 5, cc = i & 31;
        aug[i] = (cc < 16) ? Min[r * 16 + cc] : ((cc - 16 == r) ? 1.0 : 0.0);
    }
    __syncthreads();
    for (int k = 0; k < 16; ++k) {
        if (t == 0) {
            int best = k; double bv = fabs(aug[k * 32 + k]);
            for (int i = k + 1; i < 16; ++i) {
                double v = fabs(aug[i * 32 + k]);
                if (v > bv) { bv = v; best = i; }
            }
            *piv = best;
        }
        __syncthreads();
        int pb = *piv;
        if (pb != k && t < 32) {
            double tmp = aug[k * 32 + t];
            aug[k * 32 + t] = aug[pb * 32 + t];
            aug[pb * 32 + t] = tmp;
        }
        __syncthreads();
        if (t == 0) fs[16] = 1.0 / aug[k * 32 + k];
        __syncthreads();
        if (t < 32) aug[k * 32 + t] *= fs[16];
        __syncthreads();
        if (t < 16) fs[t] = aug[t * 32 + k];
        __syncthreads();
        for (int i = t; i < 512; i += TB) {
            int r = i >> 5, cc = i & 31;
            if (r != k) aug[i] -= fs[r] * aug[k * 32 + cc];
        }
        __syncthreads();
    }
    for (int i = t; i < 256; i += TB) Mout[i] = aug[(i >> 4) * 32 + 16 + (i & 15)];
    __syncthreads();
}

__device__ void matmul16d(const double* A, const double* Bm, double* Cc, int m) {
    const int t = threadIdx.x;
    for (int i = t; i < m * 16; i += TB) {
        int r = i >> 4, cc = i & 15;
        double acc = 0.0;
        #pragma unroll
        for (int x = 0; x < 16; ++x) acc += A[r * 16 + x] * Bm[x * 16 + cc];
        Cc[i] = acc;
    }
    __syncthreads();
}

__device__ void gram16d(const double* A, double* W, int m) {
    const int t = threadIdx.x;
    for (int i = t; i < 256; i += TB) {
        int r = i >> 4, cc = i & 15;
        double acc = 0.0;
        for (int x = 0; x < m; ++x) acc += A[x * 16 + r] * A[x * 16 + cc];
        W[i] = acc;
    }
    __syncthreads();
}

__device__ void vdvtd(const double* V, const double* g, double* P) {
    const int t = threadIdx.x;
    for (int i = t; i < 256; i += TB) {
        int r = i >> 4, cc = i & 15;
        double acc = 0.0;
        #pragma unroll
        for (int x = 0; x < 16; ++x) acc += V[r * 16 + x] * g[x] * V[cc * 16 + x];
        P[i] = acc;
    }
    __syncthreads();
}

// ================= kernels =================

// K1 (warp-per-instance): x_log = log_map(X[0,c], X[b,c]) -> gXlog[bc]
__global__ void __launch_bounds__(TB) k1_logmap(const float* __restrict__ X) {
    __shared__ alignas(16) double UTd[WPB][512];   // U (4KB float) -> K64/V64 or T1f/lam
    __shared__ alignas(16) float Zb[WPB][1024];
    __shared__ float Mm[WPB][272];
    __shared__ float Ww[WPB][288];
    __shared__ float Vv[WPB][288];
    const int w = threadIdx.x >> 5, lane = threadIdx.x & 31;
    const int bc = blockIdx.x * WPB + w;
    const int c = bc & (Csz - 1);
    float* U = (float*)UTd[w];
    float* Z = Zb[w];
    float* M = Mm[w];
    float* W = Ww[w];
    float* V = Vv[w];
    float* sdA = W + 272;          // 16 floats, past the stride-17 16x16 region
    const float4* Xp4 = (const float4*)(X + (size_t)bc * 1024);
    const float4* Up4 = (const float4*)(X + (size_t)c * 1024);
    float4* U4 = (float4*)U;
    float4* Z4 = (float4*)Z;
    for (int i = lane; i < 256; i += 32) { U4[i] = Up4[i]; Z4[i] = Xp4[i]; }
    __syncwarp();
    // M = U^T X
    for (int i = lane; i < 256; i += 32) {
        int r = i >> 4, cc = i & 15;
        float acc = 0.f;
        for (int x = 0; x < 64; ++x) acc += U[x * 16 + r] * Z[x * 16 + cc];
        M[r * S17 + cc] = acc;
    }
    __syncwarp();
    // Z = Z - U M
    for (int i = lane; i < 1024; i += 32) {
        int r = i >> 4, cc = i & 15;
        float acc = Z[i];
        #pragma unroll
        for (int x = 0; x < 16; ++x) acc -= U[r * 16 + x] * M[x * S17 + cc];
        Z[i] = acc;
    }
    __syncwarp();
    // W = M M^T (bounded)
    for (int i = lane; i < 256; i += 32) {
        int r = i >> 4, cc = i & 15;
        float acc = 0.f;
        #pragma unroll
        for (int x = 0; x < 16; ++x) acc += M[r * S17 + x] * M[cc * S17 + x];
        W[r * S17 + cc] = acc;
    }
    for (int i = lane; i < 288; i += 32) V[i] = 0.f;
    __syncwarp();
    if (lane < 16) V[lane * S17 + lane] = 1.f;
    jacobi_warp(W, V, lane, SWEEPS_W, true);
    // ---- post-eig: fp32 T1 + lambda; rescue to fp64 if ill-conditioned ----
    float* T1f  = (float*)UTd[w];   // 256 floats (U dead)
    float* lamA = T1f + 256;        // 16 floats
    for (int i = lane; i < 256; i += 32) {
        int r = i >> 4, cc = i & 15;
        float acc = 0.f;
        #pragma unroll
        for (int x = 0; x < 16; ++x) acc = __fmaf_rn(M[x * S17 + r], V[x * S17 + cc], acc);
        T1f[i] = acc;
    }
    __syncwarp();
    if (lane < 16) {
        float acc = 0.f;
        #pragma unroll
        for (int r = 0; r < 16; ++r) { float v = T1f[r * 16 + lane]; acc = __fmaf_rn(v, v, acc); }
        lamA[lane] = fmaxf(acc, 1e-30f);
    }
    __syncwarp();
    float lv = lamA[lane & 15];
    #pragma unroll
    for (int off = 8; off; off >>= 1) lv = fminf(lv, __shfl_xor_sync(0xffffffffu, lv, off));
    if (lv < RTOL) {
        // ===== fp64 rescue =====
        double* K64 = UTd[w];           // 256 dbl
        double* V64 = UTd[w] + 256;     // 256 dbl
        for (int i = lane; i < 256; i += 32) {
            int r = i >> 4, cc = i & 15;
            double acc = 0.0;
            #pragma unroll
            for (int x = 0; x < 16; ++x)
                acc += (double)M[r * S17 + x] * (double)M[cc * S17 + x];
            K64[i] = acc;
        }
        __syncwarp();
        jacobi_warp_d(K64, V64, lane, SWEEPS_R);
        double* T1d = K64;              // overwrite evals
        for (int i = lane; i < 256; i += 32) {
            int r = i >> 4, cc = i & 15;
            double acc = 0.0;
            #pragma unroll
            for (int x = 0; x < 16; ++x)
                acc += (double)M[x * S17 + r] * V64[x * 16 + cc];
            T1d[i] = acc;
        }
        __syncwarp();
        if (lane < 16) {
            double lh = 0.0;
            #pragma unroll
            for (int r = 0; r < 16; ++r) { double a = T1d[r * 16 + lane]; lh += a * a; }
            double lam = fmax(lh, 1e-300);
            double om = fmax(1.0 - lam, 0.0);
            double alpha = (om < 1e-28) ? 1.0 : atan(sqrt(om / lam)) / sqrt(om);
            sdA[lane] = (float)(alpha / sqrt(lam));
        }
        __syncwarp();
        // G = T1 diag(sd) V64^T (fp64 accumulate -> fp32 into W)
        for (int i = lane; i < 256; i += 32) {
            int r = i >> 4, cc = i & 15;
            double acc = 0.0;
            #pragma unroll
            for (int x = 0; x < 16; ++x)
                acc += T1d[r * 16 + x] * (double)sdA[x] * V64[cc * 16 + x];
            W[r * S17 + cc] = (float)acc;
        }
        __syncwarp();
    } else {
        // ===== fp32 fast path =====
        if (lane < 16) {
            double lam = (double)lamA[lane];
            double om = fmax(1.0 - lam, 0.0);
            double alpha = (om < 1e-28) ? 1.0 : atan(sqrt(om / lam)) / sqrt(om);
            sdA[lane] = (float)(alpha / sqrt(lam));
        }
        __syncwarp();
        // Ts into M (bounded)
        for (int i = lane; i < 256; i += 32)
            M[(i >> 4) * S17 + (i & 15)] = T1f[i] * sdA[i & 15];
        __syncwarp();
        // G = Ts V^T into W
        for (int i = lane; i < 256; i += 32) {
            int r = i >> 4, cc = i & 15;
            float acc = 0.f;
            #pragma unroll
            for (int x = 0; x < 16; ++x) acc += M[r * S17 + x] * V[cc * S17 + x];
            W[r * S17 + cc] = acc;
        }
        __syncwarp();
    }
    // x_log = Z G -> gXlog
    float4* dst4 = (float4*)(gXlog + (size_t)bc * 1024);
    for (int i4 = lane; i4 < 256; i4 += 32) {
        int r = i4 >> 2, cb = (i4 & 3) * 4;
        float a0 = 0.f, a1 = 0.f, a2 = 0.f, a3 = 0.f;
        #pragma unroll
        for (int x = 0; x < 16; ++x) {
            float z = Z[r * 16 + x];
            a0 += z * W[x * S17 + cb];
            a1 += z * W[x * S17 + cb + 1];
            a2 += z * W[x * S17 + cb + 2];
            a3 += z * W[x * S17 + cb + 3];
        }
        dst4[i4] = make_float4(a0, a1, a2, a3);
    }
}

// K2 (per channel, fp64): reduce x_log, exp_map mean, Bm, GinvC
__global__ void k2_mean(const float* __restrict__ X, float* __restrict__ meanOut) {
    __shared__ double Dm[1024], U0[1024], meanS[1024], Cm[768];
    __shared__ double W[256], V[256], M1[256], M2[256], aug[512];
    __shared__ double g[32], cs[16], fs[18];
    __shared__ int piv;
    const int c = blockIdx.x;
    const int t = threadIdx.x;
    const float4* gX4 = (const float4*)gXlog;
    for (int i4 = t; i4 < 256; i4 += TB) {
        double a0 = 0.0, a1 = 0.0, a2 = 0.0, a3 = 0.0;
        #pragma unroll 4
        for (int b = 0; b < Bsz; ++b) {
            float4 v = gX4[((size_t)b * Csz + c) * 256 + i4];
            a0 += v.x; a1 += v.y; a2 += v.z; a3 += v.w;
        }
        const double inv = 1.0 / (double)Bsz;
        int i = i4 * 4;
        Dm[i] = a0 * inv; Dm[i + 1] = a1 * inv; Dm[i + 2] = a2 * inv; Dm[i + 3] = a3 * inv;
    }
    for (int i = t; i < 1024; i += TB)
        U0[i] = (double)X[(size_t)c * 1024 + i];
    __syncthreads();
    gram16d(Dm, W, 64);
    jacobi16d(W, V, cs);
    if (t < 16) {
        double S = sqrt(fmax(W[t * 17], 0.0));
        g[t] = cos(S);
        g[16 + t] = (S > 1e-100) ? sin(S) / S : 1.0;
    }
    __syncthreads();
    vdvtd(V, g, M1);
    vdvtd(V, g + 16, M2);
    for (int i = t; i < 1024; i += TB) {
        int r = i >> 4, cc = i & 15;
        double acc = 0.0;
        #pragma unroll
        for (int x = 0; x < 16; ++x)
            acc += U0[r * 16 + x] * M1[x * 16 + cc] + Dm[r * 16 + x] * M2[x * 16 + cc];
        meanS[i] = acc;
        meanOut[c * 1024 + i] = (float)acc;
    }
    __syncthreads();
    invert16d(meanS, aug, M1, fs, &piv);
    matmul16d(meanS + 256, M1, Cm, 48);
    gram16d(Cm, W, 48);
    jacobi16d(W, V, cs);
    if (t < 16) {
        double S = sqrt(fmax(W[t * 17], 0.0));
        g[t] = (S > 1e-100) ? atan(S) / S : 1.0;
    }
    __syncthreads();
    vdvtd(V, g, M2);
    matmul16d(Cm, M2, Dm, 48);
    for (int i = t; i < 768; i += TB) gBmF[c * 768 + i] = (float)Dm[i];
    __syncthreads();
    gram16d(Dm, W, 48);
    for (int i = t; i < 256; i += TB) {
        int r = i >> 4, cc = i & 15;
        W[i] = 0.25 * W[i] + ((r == cc) ? 1.0 : 0.0);
    }
    __syncthreads();
    invert16d(W, aug, M1, fs, &piv);
    for (int i = t; i < 256; i += TB) gGinvCF[c * 256 + i] = (float)M1[i];
}

// K3 (warp-per-instance): theta^2 sum -> gTheta[bc]
__global__ void __launch_bounds__(TB) k3_theta(const float* __restrict__ X,
                                               const float* __restrict__ meanIn) {
    __shared__ alignas(16) float Mn[WPB][1024];
    __shared__ alignas(16) float Xb[WPB][1024];
    __shared__ float Mm[WPB][272], Ww[WPB][288];
    const int w = threadIdx.x >> 5, lane = threadIdx.x & 31;
    const int bc = blockIdx.x * WPB + w;
    const int c = bc & (Csz - 1);
    float* A = Mn[w];
    float* Xl = Xb[w];
    float* M = Mm[w];
    float* W = Ww[w];
    const float4* Xp4 = (const float4*)(X + (size_t)bc * 1024);
    const float4* Mp4 = (const float4*)(meanIn + (size_t)c * 1024);
    float4* A4 = (float4*)A;
    float4* Xl4 = (float4*)Xl;
    for (int i = lane; i < 256; i += 32) { A4[i] = Mp4[i]; Xl4[i] = Xp4[i]; }
    __syncwarp();
    for (int i = lane; i < 256; i += 32) {
        int r = i >> 4, cc = i & 15;
        float acc = 0.f;
        for (int x = 0; x < 64; ++x) acc += A[x * 16 + r] * Xl[x * 16 + cc];
        M[r * S17 + cc] = acc;
    }
    __syncwarp();
    for (int i = lane; i < 256; i += 32) {
        int r = i >> 4, cc = i & 15;
        float acc = 0.f;
        #pragma unroll
        for (int x = 0; x < 16; ++x) acc += M[x * S17 + r] * M[x * S17 + cc];
        W[r * S17 + cc] = acc;
    }
    jacobi_warp(W, (float*)0, lane, SWEEPS_NV, false);
    if (lane == 0) {
        float sum = 0.f;
        for (int j2 = 0; j2 < 16; ++j2) {
            float s = sqrtf(fmaxf(W[j2 * 18], 0.f));
            s = fminf(s, 1.f);
            float th = acosf(s);
            sum += th * th;
        }
        gTheta[bc] = sum;
    }
}

// K4 (grid=Csz): per-channel factor via tree reduction; block 0 also bias Ginv
__global__ void k4_factor(const float* __restrict__ bias, const float* __restrict__ shiftp) {
    __shared__ float red[TB];
    __shared__ double Bb[768], W[256], M1[256], aug[512], fs[18];
    __shared__ int piv;
    const int t = threadIdx.x;
    const int c = blockIdx.x;
    red[t] = gTheta[t * Csz + c] + gTheta[(t + TB) * Csz + c];
    __syncthreads();
    for (int s = TB / 2; s > 0; s >>= 1) {
        if (t < s) red[t] += red[t + s];
        __syncthreads();
    }
    if (t == 0) {
        double var = (double)red[0] * (1.0 / (double)Bsz);
        gFactorF[c] = (float)((double)shiftp[0] / sqrt(var + 1e-5));
    }
    if (c == 0) {
        for (int i = t; i < 768; i += TB) Bb[i] = (double)bias[i];
        __syncthreads();
        gram16d(Bb, W, 48);
        for (int i = t; i < 256; i += TB) {
            int r = i >> 4, cc = i & 15;
            W[i] = 0.25 * W[i] + ((r == cc) ? 1.0 : 0.0);
        }
        __syncthreads();
        invert16d(W, aug, M1, fs, &piv);
        for (int i = t; i < 256; i += TB) gGinvBF[i] = (float)M1[i];
    }
}

// K5 (warp-per-instance): center -> gyro scale -> bias
__global__ void __launch_bounds__(TB) k5_final(const float* __restrict__ X,
                                               const float* __restrict__ bias,
                                               float* __restrict__ out) {
    __shared__ alignas(16) float Xs[WPB][1024];
    __shared__ alignas(16) float Bmw[WPB][768];   // Bm -> (rescue V64) -> bot -> bias
    __shared__ alignas(16) double bufd[WPB][256]; // Ginv/W/T1f or rescue K64/T1d
    __shared__ float Vv[WPB][288];
    __shared__ alignas(16) float Tt[WPB][256];
    __shared__ float lamK[WPB][16], sdK[WPB][16], gkK[WPB][16];
    const int w = threadIdx.x >> 5, lane = threadIdx.x & 31;
    const int bc = blockIdx.x * WPB + w;
    const int c = bc & (Csz - 1);
    float* Xw = Xs[w];
    float* Bw = Bmw[w];
    float* buf_f = (float*)bufd[w];
    float* V = Vv[w];
    float* T = Tt[w];
    {
        const float4* Xp4 = (const float4*)(X + (size_t)bc * 1024);
        const float4* Bm4 = (const float4*)(gBmF + (size_t)c * 768);
        const float4* Gi4 = (const float4*)(gGinvCF + (size_t)c * 256);
        float4* Xw4 = (float4*)Xw;
        float4* Bw4 = (float4*)Bw;
        float4* bf4 = (float4*)buf_f;
        for (int i = lane; i < 256; i += 32) Xw4[i] = Xp4[i];
        for (int i = lane; i < 192; i += 32) Bw4[i] = Bm4[i];
        for (int i = lane; i < 64; i += 32) bf4[i] = Gi4[i];
    }
    __syncwarp();
    // --- Step A: centering Cayley ---
    for (int i = lane; i < 256; i += 32) {
        int r = i >> 4, cc = i & 15;
        float acc = Xw[i];
        for (int k = 0; k < 48; ++k)
            acc += 0.5f * Bw[k * 16 + r] * Xw[256 + k * 16 + cc];
        T[i] = acc;
    }
    __syncwarp();
    {
        float yreg[8];
        #pragma unroll
        for (int ii = 0; ii < 8; ++ii) {
            int i = lane + 32 * ii, r = i >> 4, cc = i & 15;
            float acc = 0.f;
            #pragma unroll
            for (int x = 0; x < 16; ++x) acc += buf_f[r * 16 + x] * T[x * 16 + cc];
            yreg[ii] = acc;
        }
        __syncwarp();
        #pragma unroll
        for (int ii = 0; ii < 8; ++ii) T[lane + 32 * ii] = yreg[ii];
    }
    __syncwarp();
    for (int i = lane; i < 1024; i += 32) {
        if (i < 256) Xw[i] = 2.f * T[i] - Xw[i];
        else {
            int r = (i - 256) >> 4, cc = i & 15;
            float acc = Xw[i];
            #pragma unroll
            for (int x = 0; x < 16; ++x) acc -= Bw[r * 16 + x] * T[x * 16 + cc];
            Xw[i] = acc;
        }
    }
    __syncwarp();
    // --- Step B: gyro scaling via K = Xu Xu^T ---
    float* W = buf_f;
    for (int i = lane; i < 256; i += 32) {
        int r = i >> 4, cc = i & 15;
        float acc = 0.f;
        #pragma unroll
        for (int x = 0; x < 16; ++x) acc += Xw[r * 16 + x] * Xw[cc * 16 + x];
        W[r * S17 + cc] = acc;
    }
    for (int i = lane; i < 288; i += 32) V[i] = 0.f;
    __syncwarp();
    if (lane < 16) V[lane * S17 + lane] = 1.f;
    jacobi_warp(W, V, lane, SWEEPS_W, true);
    // ---- T1 fp32 + lambda; rescue if ill-conditioned ----
    float* T1f = buf_f;          // 256 (W dead)
    for (int i = lane; i < 256; i += 32) {
        int r = i >> 4, cc = i & 15;
        float acc = 0.f;
        #pragma unroll
        for (int x = 0; x < 16; ++x) acc = __fmaf_rn(Xw[x * 16 + r], V[x * S17 + cc], acc);
        T1f[i] = acc;
    }
    __syncwarp();
    if (lane < 16) {
        float acc = 0.f;
        #pragma unroll
        for (int r = 0; r < 16; ++r) { float v = T1f[r * 16 + lane]; acc = __fmaf_rn(v, v, acc); }
        lamK[w][lane] = fmaxf(acc, 1e-30f);
    }
    __syncwarp();
    float fct = gFactorF[c];
    float lv = lamK[w][lane & 15];
    #pragma unroll
    for (int off = 8; off; off >>= 1) lv = fminf(lv, __shfl_xor_sync(0xffffffffu, lv, off));
    if (lv < RTOL) {
        // ===== fp64 rescue =====
        double* K64 = bufd[w];              // 256 dbl (T1f dead)
        double* V64 = (double*)Bmw[w];      // 256 dbl (Bm dead)
        for (int i = lane; i < 256; i += 32) {
            int r = i >> 4, cc = i & 15;
            double acc = 0.0;
            #pragma unroll
            for (int x = 0; x < 16; ++x)
                acc += (double)Xw[r * 16 + x] * (double)Xw[cc * 16 + x];
            K64[i] = acc;
        }
        __syncwarp();
        jacobi_warp_d(K64, V64, lane, SWEEPS_R);
        double* T1d = K64;
        for (int i = lane; i < 256; i += 32) {
            int r = i >> 4, cc = i & 15;
            double acc = 0.0;
            #pragma unroll
            for (int x = 0; x < 16; ++x)
                acc += (double)Xw[x * 16 + r] * V64[x * 16 + cc];
            T1d[i] = acc;
        }
        __syncwarp();
        if (lane < 16) {
            double lh = 0.0;
            #pragma unroll
            for (int r = 0; r < 16; ++r) { double a = T1d[r * 16 + lane]; lh += a * a; }
            double lam = fmax(lh, 1e-300);
            double om = fmax(1.0 - lam, 0.0);
            double beta, cth;
            if (om < 1e-28) { beta = (double)fct; cth = 1.0; }
            else {
                double th = (double)fct * atan(sqrt(om / lam));
                beta = sin(th) / sqrt(om);
                cth = cos(th);
            }
            sdK[w][lane] = (float)(beta / sqrt(lam));
            gkK[w][lane] = (float)cth;
        }
        __syncwarp();
        // M2 = T1 diag(sd) V64^T (fp64) -> stage regs -> fp32 into Vv (V32 dead)
        {
            float m2reg[8];
            #pragma unroll
            for (int ii = 0; ii < 8; ++ii) {
                int i = lane + 32 * ii, r = i >> 4, cc = i & 15;
                double acc = 0.0;
                #pragma unroll
                for (int x = 0; x < 16; ++x)
                    acc += T1d[r * 16 + x] * (double)sdK[w][x] * V64[cc * 16 + x];
                m2reg[ii] = (float)acc;
            }
            // top = V64 diag(cth) V64^T -> T
            for (int i = lane; i < 256; i += 32) {
                int r = i >> 4, cc = i & 15;
                double acc = 0.0;
                #pragma unroll
                for (int x = 0; x < 16; ++x)
                    acc += V64[r * 16 + x] * (double)gkK[w][x] * V64[cc * 16 + x];
                T[i] = (float)acc;
            }
            __syncwarp();
            #pragma unroll
            for (int ii = 0; ii < 8; ++ii) V[lane + 32 * ii] = m2reg[ii];
        }
        __syncwarp();
        // bot = Xl M2 into Bw (V64 dead now)
        for (int i = lane; i < 768; i += 32) {
            int r = i >> 4, cc = i & 15;
            float acc = 0.f;
            #pragma unroll
            for (int x = 0; x < 16; ++x) acc += Xw[256 + r * 16 + x] * V[x * 16 + cc];
            Bw[i] = acc;
        }
        __syncwarp();
    } else {
        // ===== fp32 fast path =====
        if (lane < 16) {
            double lam = (double)lamK[w][lane];
            double om = fmax(1.0 - lam, 0.0);
            double beta, cth;
            if (om < 1e-28) { beta = (double)fct; cth = 1.0; }
            else {
                double th = (double)fct * atan(sqrt(om / lam));
                beta = sin(th) / sqrt(om);
                cth = cos(th);
            }
            sdK[w][lane] = (float)(beta / sqrt(lam));
            gkK[w][lane] = (float)cth;
        }
        __syncwarp();
        // Ts into buf_f+256
        float* Tsf = buf_f + 256;
        for (int i = lane; i < 256; i += 32) Tsf[i] = T1f[i] * sdK[w][i & 15];
        __syncwarp();
        // M2 = Ts V^T -> stage regs -> into Vv? No: keep M2 in Vv for unified downstream.
        {
            float m2reg[8];
            #pragma unroll
            for (int ii = 0; ii < 8; ++ii) {
                int i = lane + 32 * ii, r = i >> 4, cc = i & 15;
                float acc = 0.f;
                #pragma unroll
                for (int x = 0; x < 16; ++x) acc += Tsf[r * 16 + x] * V[cc * S17 + x];
                m2reg[ii] = acc;
            }
            // top = V cos V^T into T (uses V32 before overwrite)
            float topreg[8];
            #pragma unroll
            for (int ii = 0; ii < 8; ++ii) {
                int i = lane + 32 * ii, r = i >> 4, cc = i & 15;
                float acc = 0.f;
                #pragma unroll
                for (int x = 0; x < 16; ++x) acc += V[r * S17 + x] * gkK[w][x] * V[cc * S17 + x];
                topreg[ii] = acc;
            }
            __syncwarp();
            #pragma unroll
            for (int ii = 0; ii < 8; ++ii) {
                V[lane + 32 * ii] = m2reg[ii];      // M2 into Vv[0..255]
                T[lane + 32 * ii] = topreg[ii];
            }
        }
        __syncwarp();
        // bot = Xl M2 into Bw
        for (int i = lane; i < 768; i += 32) {
            int r = i >> 4, cc = i & 15;
            float acc = 0.f;
            #pragma unroll
            for (int x = 0; x < 16; ++x) acc += Xw[256 + r * 16 + x] * V[x * 16 + cc];
            Bw[i] = acc;
        }
        __syncwarp();
    }
    // commit: Xu=top, Xl=bot
    {
        float4* Xw4 = (float4*)Xw;
        float4* T4 = (float4*)T;
        float4* Bw4 = (float4*)Bw;
        for (int i = lane; i < 64; i += 32) Xw4[i] = T4[i];
        for (int i = lane; i < 192; i += 32) Xw4[64 + i] = Bw4[i];
    }
    __syncwarp();
    // --- Step C: bias Cayley ---
    {
        const float4* b4 = (const float4*)bias;
        const float4* g4 = (const float4*)gGinvBF;
        float4* Bw4 = (float4*)Bw;
        float4* bf4 = (float4*)buf_f;
        for (int i = lane; i < 192; i += 32) Bw4[i] = b4[i];
        for (int i = lane; i < 64; i += 32) bf4[i] = g4[i];
    }
    __syncwarp();
    for (int i = lane; i < 256; i += 32) {
        int r = i >> 4, cc = i & 15;
        float acc = Xw[i];
        for (int k = 0; k < 48; ++k)
            acc -= 0.5f * Bw[k * 16 + r] * Xw[256 + k * 16 + cc];
        T[i] = acc;
    }
    __syncwarp();
    {
        float yreg[8];
        #pragma unroll
        for (int ii = 0; ii < 8; ++ii) {
            int i = lane + 32 * ii, r = i >> 4, cc = i & 15;
            float acc = 0.f;
            #pragma unroll
            for (int x = 0; x < 16; ++x) acc += buf_f[r * 16 + x] * T[x * 16 + cc];
            yreg[ii] = acc;
        }
        __syncwarp();
        #pragma unroll
        for (int ii = 0; ii < 8; ++ii) T[lane + 32 * ii] = yreg[ii];
    }
    __syncwarp();
    float4* dst4 = (float4*)(out + (size_t)bc * 1024);
    for (int i4 = lane; i4 < 64; i4 += 32) {
        float4 t4 = ((float4*)T)[i4];
        float4 x4 = ((float4*)Xw)[i4];
        dst4[i4] = make_float4(2.f * t4.x - x4.x, 2.f * t4.y - x4.y,
                               2.f * t4.z - x4.z, 2.f * t4.w - x4.w);
    }
    for (int i4 = lane; i4 < 192; i4 += 32) {
        int r = i4 >> 2, cb = (i4 & 3) * 4;
        float a0 = Xw[256 + r * 16 + cb];
        float a1 = Xw[256 + r * 16 + cb + 1];
        float a2 = Xw[256 + r * 16 + cb + 2];
        float a3 = Xw[256 + r * 16 + cb + 3];
        #pragma unroll
        for (int x = 0; x < 16; ++x) {
            float bv = Bw[r * 16 + x];
            a0 += bv * T[x * 16 + cb];
            a1 += bv * T[x * 16 + cb + 1];
            a2 += bv * T[x * 16 + cb + 2];
            a3 += bv * T[x * 16 + cb + 3];
        }
        dst4[64 + i4] = make_float4(a0, a1, a2, a3);
    }
}

// ---------------- launch ----------------
extern "C" void kernel_launch(void* const* d_in, const int* in_sizes, int n_in,
                              void* d_out, int out_size) {
    const float* X = (const float*)d_in[0];
    const float* bias = (const float*)d_in[1];
    const float* shift = (const float*)d_in[2];
    float* out = (float*)d_out;
    float* meanOut = out + (size_t)Bsz * Csz * Nsz * Psz;

    const int nInst = Bsz * Csz;
    k1_logmap<<<nInst / WPB, TB>>>(X);
    k2_mean<<<Csz, TB>>>(X, meanOut);
    k3_theta<<<nInst / WPB, TB>>>(X, meanOut);
    k4_factor<<<Csz, TB>>>(bias, shift);
    k5_final<<<nInst / WPB, TB>>>(X, bias, out);
}

// round 10
// speedup vs baseline: 7.3968x; 7.3968x over previous
#include <cuda_runtime.h>

#define Bsz 256
#define Csz 128
#define Nsz 64
#define Psz 16
#define Qsz 48
#define TB 128
#define WPB 4
#define SWEEPS_W 6
#define SWEEPS_NV 4
#define SWEEPS_D 5
#define S17 17

// ---------------- device scratch (static, no allocations) ----------------
__device__ alignas(16) float gXlog[(size_t)Bsz * Csz * Nsz * Psz]; // 128MB
__device__ float gTheta[Bsz * Csz];
__device__ alignas(16) float gBmF[Csz * Qsz * Psz];
__device__ alignas(16) float gGinvCF[Csz * Psz * Psz];
__device__ alignas(16) float gGinvBF[Psz * Psz];
__device__ float gFactorF[Csz];

// ================= warp-level fp32 Jacobi (stride-17 smem) =================
__device__ __forceinline__ void jacobi_warp(float* W, float* V, int lane,
                                            int sweeps, bool wantV) {
    const int j = lane >> 2;
    const int b4 = (lane & 3) * 4;
    for (int sweep = 0; sweep < sweeps; ++sweep) {
        for (int r = 0; r < 15; ++r) {
            int p, q;
            if (j == 0) { p = 15; q = r; }
            else { p = (r + j) % 15; q = (r + 15 - j) % 15; }
            if (p < q) { int tmp = p; p = q; q = tmp; }
            __syncwarp();
            float c = 1.f, s = 0.f;
            if ((lane & 3) == 0) {
                float app = W[p * S17 + p], aqq = W[q * S17 + q], apq = W[p * S17 + q];
                if (fabsf(apq) > 1e-37f) {
                    float tau = (aqq - app) / (2.f * apq);
                    float tt = copysignf(1.f, tau) / (fabsf(tau) + sqrtf(1.f + tau * tau));
                    c = rsqrtf(1.f + tt * tt);
                    s = tt * c;
                }
            }
            c = __shfl_sync(0xffffffffu, c, lane & ~3);
            s = __shfl_sync(0xffffffffu, s, lane & ~3);
            #pragma unroll
            for (int k = 0; k < 4; ++k) {
                int col = b4 + k;
                float wp = W[p * S17 + col], wq = W[q * S17 + col];
                W[p * S17 + col] = c * wp - s * wq;
                W[q * S17 + col] = s * wp + c * wq;
            }
            __syncwarp();
            #pragma unroll
            for (int k = 0; k < 4; ++k) {
                int row = b4 + k;
                float xp = W[row * S17 + p], xq = W[row * S17 + q];
                W[row * S17 + p] = c * xp - s * xq;
                W[row * S17 + q] = s * xp + c * xq;
                if (wantV) {
                    float vp = V[row * S17 + p], vq = V[row * S17 + q];
                    V[row * S17 + p] = c * vp - s * vq;
                    V[row * S17 + q] = s * vp + c * vq;
                }
            }
        }
    }
    __syncwarp();
}

// ================= block-level fp64 helpers (k2/k4) =================
__device__ void jacobi16d(double* W, double* V, double* cs) {
    const int t = threadIdx.x;
    for (int i = t; i < 256; i += TB) V[i] = ((i >> 4) == (i & 15)) ? 1.0 : 0.0;
    __syncthreads();
    const int pr = t >> 4, el = t & 15;
    for (int sweep = 0; sweep < SWEEPS_D; ++sweep) {
        for (int r = 0; r < 15; ++r) {
            int p, q;
            if (pr == 0) { p = 15; q = r; }
            else { p = (r + pr) % 15; q = (r + 15 - pr) % 15; }
            if (p < q) { int tmp = p; p = q; q = tmp; }
            if (el == 0) {
                double app = W[p * 16 + p], aqq = W[q * 16 + q], apq = W[p * 16 + q];
                double c = 1.0, s = 0.0;
                if (fabs(apq) > 1e-300) {
                    double tau = (aqq - app) / (2.0 * apq);
                    double tt = copysign(1.0, tau) / (fabs(tau) + sqrt(1.0 + tau * tau));
                    c = rsqrt(1.0 + tt * tt);
                    s = tt * c;
                }
                cs[pr] = c; cs[8 + pr] = s;
            }
            __syncthreads();
            double c = cs[pr], s = cs[8 + pr];
            double wp = W[p * 16 + el], wq = W[q * 16 + el];
            W[p * 16 + el] = c * wp - s * wq;
            W[q * 16 + el] = s * wp + c * wq;
            __syncthreads();
            double xp = W[el * 16 + p], xq = W[el * 16 + q];
            W[el * 16 + p] = c * xp - s * xq;
            W[el * 16 + q] = s * xp + c * xq;
            double vp = V[el * 16 + p], vq = V[el * 16 + q];
            V[el * 16 + p] = c * vp - s * vq;
            V[el * 16 + q] = s * vp + c * vq;
            __syncthreads();
        }
    }
}

__device__ void invert16d(const double* Min, double* aug, double* Mout, double* fs, int* piv) {
    const int t = threadIdx.x;
    for (int i = t; i < 512; i += TB) {
        int r = i >> 5, cc = i & 31;
        aug[i] = (cc < 16) ? Min[r * 16 + cc] : ((cc - 16 == r) ? 1.0 : 0.0);
    }
    __syncthreads();
    for (int k = 0; k < 16; ++k) {
        if (t == 0) {
            int best = k; double bv = fabs(aug[k * 32 + k]);
            for (int i = k + 1; i < 16; ++i) {
                double v = fabs(aug[i * 32 + k]);
                if (v > bv) { bv = v; best = i; }
            }
            *piv = best;
        }
        __syncthreads();
        int pb = *piv;
        if (pb != k && t < 32) {
            double tmp = aug[k * 32 + t];
            aug[k * 32 + t] = aug[pb * 32 + t];
            aug[pb * 32 + t] = tmp;
        }
        __syncthreads();
        if (t == 0) fs[16] = 1.0 / aug[k * 32 + k];
        __syncthreads();
        if (t < 32) aug[k * 32 + t] *= fs[16];
        __syncthreads();
        if (t < 16) fs[t] = aug[t * 32 + k];
        __syncthreads();
        for (int i = t; i < 512; i += TB) {
            int r = i >> 5, cc = i & 31;
            if (r != k) aug[i] -= fs[r] * aug[k * 32 + cc];
        }
        __syncthreads();
    }
    for (int i = t; i < 256; i += TB) Mout[i] = aug[(i >> 4) * 32 + 16 + (i & 15)];
    __syncthreads();
}

__device__ void matmul16d(const double* A, const double* Bm, double* Cc, int m) {
    const int t = threadIdx.x;
    for (int i = t; i < m * 16; i += TB) {
        int r = i >> 4, cc = i & 15;
        double acc = 0.0;
        #pragma unroll
        for (int x = 0; x < 16; ++x) acc += A[r * 16 + x] * Bm[x * 16 + cc];
        Cc[i] = acc;
    }
    __syncthreads();
}

__device__ void gram16d(const double* A, double* W, int m) {
    const int t = threadIdx.x;
    for (int i = t; i < 256; i += TB) {
        int r = i >> 4, cc = i & 15;
        double acc = 0.0;
        for (int x = 0; x < m; ++x) acc += A[x * 16 + r] * A[x * 16 + cc];
        W[i] = acc;
    }
    __syncthreads();
}

__device__ void vdvtd(const double* V, const double* g, double* P) {
    const int t = threadIdx.x;
    for (int i = t; i < 256; i += TB) {
        int r = i >> 4, cc = i & 15;
        double acc = 0.0;
        #pragma unroll
        for (int x = 0; x < 16; ++x) acc += V[r * 16 + x] * g[x] * V[cc * 16 + x];
        P[i] = acc;
    }
    __syncthreads();
}

// ================= kernels =================

// K1 (warp-per-instance): x_log = log_map(X[0,c], X[b,c]) -> gXlog[bc]
__global__ void __launch_bounds__(TB) k1_logmap(const float* __restrict__ X) {
    __shared__ alignas(16) float Ub[WPB][1024];   // U -> T1f/lam scratch
    __shared__ alignas(16) float Zb[WPB][1024];
    __shared__ float Mm[WPB][272];
    __shared__ float Ww[WPB][288];
    __shared__ float Vv[WPB][288];
    const int w = threadIdx.x >> 5, lane = threadIdx.x & 31;
    const int bc = blockIdx.x * WPB + w;
    const int c = bc & (Csz - 1);
    float* U = Ub[w];
    float* Z = Zb[w];
    float* M = Mm[w];
    float* W = Ww[w];
    float* V = Vv[w];
    float* sdA = W + 272;          // 16 floats past the stride-17 16x16 region
    const float4* Xp4 = (const float4*)(X + (size_t)bc * 1024);
    const float4* Up4 = (const float4*)(X + (size_t)c * 1024);
    float4* U4 = (float4*)U;
    float4* Z4 = (float4*)Z;
    for (int i = lane; i < 256; i += 32) { U4[i] = Up4[i]; Z4[i] = Xp4[i]; }
    __syncwarp();
    // M = U^T X
    for (int i = lane; i < 256; i += 32) {
        int r = i >> 4, cc = i & 15;
        float acc = 0.f;
        for (int x = 0; x < 64; ++x) acc += U[x * 16 + r] * Z[x * 16 + cc];
        M[r * S17 + cc] = acc;
    }
    __syncwarp();
    // Z = Z - U M
    for (int i = lane; i < 1024; i += 32) {
        int r = i >> 4, cc = i & 15;
        float acc = Z[i];
        #pragma unroll
        for (int x = 0; x < 16; ++x) acc -= U[r * 16 + x] * M[x * S17 + cc];
        Z[i] = acc;
    }
    __syncwarp();
    // W = M M^T (bounded)
    for (int i = lane; i < 256; i += 32) {
        int r = i >> 4, cc = i & 15;
        float acc = 0.f;
        #pragma unroll
        for (int x = 0; x < 16; ++x) acc += M[r * S17 + x] * M[cc * S17 + x];
        W[r * S17 + cc] = acc;
    }
    for (int i = lane; i < 288; i += 32) V[i] = 0.f;
    __syncwarp();
    if (lane < 16) V[lane * S17 + lane] = 1.f;
    jacobi_warp(W, V, lane, SWEEPS_W, true);
    // ---- post-eig: compensated fp32 T1 (U dead) ----
    float* T1f  = U;                // 256 floats
    float* lamA = U + 256;          // 16 floats
    for (int i = lane; i < 256; i += 32) {
        int r = i >> 4, cc = i & 15;
        float s = 0.f, comp = 0.f;
        #pragma unroll
        for (int x = 0; x < 16; ++x) {
            float a = M[x * S17 + r], b = V[x * S17 + cc];
            float p = __fmul_rn(a, b);
            float e = __fmaf_rn(a, b, -p);
            float y = p - comp;
            float t2 = s + y;
            comp = ((t2 - s) - y) - e;
            s = t2;
        }
        T1f[i] = s - comp;
    }
    __syncwarp();
    if (lane < 16) {
        float acc = 0.f;
        #pragma unroll
        for (int r = 0; r < 16; ++r) { float v = T1f[r * 16 + lane]; acc = __fmaf_rn(v, v, acc); }
        lamA[lane] = fmaxf(acc, 1e-30f);
    }
    __syncwarp();
    if (lane < 16) {
        double lam = (double)lamA[lane];
        double om = fmax(1.0 - lam, 0.0);
        double alpha = (om < 1e-28) ? 1.0 : atan(sqrt(om / lam)) / sqrt(om);
        sdA[lane] = (float)(alpha / sqrt(lam));
    }
    __syncwarp();
    // Ts into M (bounded)
    for (int i = lane; i < 256; i += 32)
        M[(i >> 4) * S17 + (i & 15)] = T1f[i] * sdA[i & 15];
    __syncwarp();
    // G = Ts V^T into W
    for (int i = lane; i < 256; i += 32) {
        int r = i >> 4, cc = i & 15;
        float acc = 0.f;
        #pragma unroll
        for (int x = 0; x < 16; ++x) acc += M[r * S17 + x] * V[cc * S17 + x];
        W[r * S17 + cc] = acc;
    }
    __syncwarp();
    // x_log = Z G -> gXlog
    float4* dst4 = (float4*)(gXlog + (size_t)bc * 1024);
    for (int i4 = lane; i4 < 256; i4 += 32) {
        int r = i4 >> 2, cb = (i4 & 3) * 4;
        float a0 = 0.f, a1 = 0.f, a2 = 0.f, a3 = 0.f;
        #pragma unroll
        for (int x = 0; x < 16; ++x) {
            float z = Z[r * 16 + x];
            a0 += z * W[x * S17 + cb];
            a1 += z * W[x * S17 + cb + 1];
            a2 += z * W[x * S17 + cb + 2];
            a3 += z * W[x * S17 + cb + 3];
        }
        dst4[i4] = make_float4(a0, a1, a2, a3);
    }
}

// K2 (per channel, fp64): reduce x_log, exp_map mean, Bm, GinvC
__global__ void k2_mean(const float* __restrict__ X, float* __restrict__ meanOut) {
    __shared__ double Dm[1024], U0[1024], meanS[1024], Cm[768];
    __shared__ double W[256], V[256], M1[256], M2[256], aug[512];
    __shared__ double g[32], cs[16], fs[18];
    __shared__ int piv;
    const int c = blockIdx.x;
    const int t = threadIdx.x;
    const float4* gX4 = (const float4*)gXlog;
    for (int i4 = t; i4 < 256; i4 += TB) {
        double a0 = 0.0, a1 = 0.0, a2 = 0.0, a3 = 0.0;
        #pragma unroll 4
        for (int b = 0; b < Bsz; ++b) {
            float4 v = gX4[((size_t)b * Csz + c) * 256 + i4];
            a0 += v.x; a1 += v.y; a2 += v.z; a3 += v.w;
        }
        const double inv = 1.0 / (double)Bsz;
        int i = i4 * 4;
        Dm[i] = a0 * inv; Dm[i + 1] = a1 * inv; Dm[i + 2] = a2 * inv; Dm[i + 3] = a3 * inv;
    }
    for (int i = t; i < 1024; i += TB)
        U0[i] = (double)X[(size_t)c * 1024 + i];
    __syncthreads();
    gram16d(Dm, W, 64);
    jacobi16d(W, V, cs);
    if (t < 16) {
        double S = sqrt(fmax(W[t * 17], 0.0));
        g[t] = cos(S);
        g[16 + t] = (S > 1e-100) ? sin(S) / S : 1.0;
    }
    __syncthreads();
    vdvtd(V, g, M1);
    vdvtd(V, g + 16, M2);
    for (int i = t; i < 1024; i += TB) {
        int r = i >> 4, cc = i & 15;
        double acc = 0.0;
        #pragma unroll
        for (int x = 0; x < 16; ++x)
            acc += U0[r * 16 + x] * M1[x * 16 + cc] + Dm[r * 16 + x] * M2[x * 16 + cc];
        meanS[i] = acc;
        meanOut[c * 1024 + i] = (float)acc;
    }
    __syncthreads();
    invert16d(meanS, aug, M1, fs, &piv);
    matmul16d(meanS + 256, M1, Cm, 48);
    gram16d(Cm, W, 48);
    jacobi16d(W, V, cs);
    if (t < 16) {
        double S = sqrt(fmax(W[t * 17], 0.0));
        g[t] = (S > 1e-100) ? atan(S) / S : 1.0;
    }
    __syncthreads();
    vdvtd(V, g, M2);
    matmul16d(Cm, M2, Dm, 48);
    for (int i = t; i < 768; i += TB) gBmF[c * 768 + i] = (float)Dm[i];
    __syncthreads();
    gram16d(Dm, W, 48);
    for (int i = t; i < 256; i += TB) {
        int r = i >> 4, cc = i & 15;
        W[i] = 0.25 * W[i] + ((r == cc) ? 1.0 : 0.0);
    }
    __syncthreads();
    invert16d(W, aug, M1, fs, &piv);
    for (int i = t; i < 256; i += TB) gGinvCF[c * 256 + i] = (float)M1[i];
}

// K3 (warp-per-instance): theta^2 sum -> gTheta[bc]
__global__ void __launch_bounds__(TB) k3_theta(const float* __restrict__ X,
                                               const float* __restrict__ meanIn) {
    __shared__ alignas(16) float Mn[WPB][1024];
    __shared__ alignas(16) float Xb[WPB][1024];
    __shared__ float Mm[WPB][272], Ww[WPB][288];
    const int w = threadIdx.x >> 5, lane = threadIdx.x & 31;
    const int bc = blockIdx.x * WPB + w;
    const int c = bc & (Csz - 1);
    float* A = Mn[w];
    float* Xl = Xb[w];
    float* M = Mm[w];
    float* W = Ww[w];
    const float4* Xp4 = (const float4*)(X + (size_t)bc * 1024);
    const float4* Mp4 = (const float4*)(meanIn + (size_t)c * 1024);
    float4* A4 = (float4*)A;
    float4* Xl4 = (float4*)Xl;
    for (int i = lane; i < 256; i += 32) { A4[i] = Mp4[i]; Xl4[i] = Xp4[i]; }
    __syncwarp();
    for (int i = lane; i < 256; i += 32) {
        int r = i >> 4, cc = i & 15;
        float acc = 0.f;
        for (int x = 0; x < 64; ++x) acc += A[x * 16 + r] * Xl[x * 16 + cc];
        M[r * S17 + cc] = acc;
    }
    __syncwarp();
    for (int i = lane; i < 256; i += 32) {
        int r = i >> 4, cc = i & 15;
        float acc = 0.f;
        #pragma unroll
        for (int x = 0; x < 16; ++x) acc += M[x * S17 + r] * M[x * S17 + cc];
        W[r * S17 + cc] = acc;
    }
    jacobi_warp(W, (float*)0, lane, SWEEPS_NV, false);
    if (lane == 0) {
        float sum = 0.f;
        for (int j2 = 0; j2 < 16; ++j2) {
            float s = sqrtf(fmaxf(W[j2 * 18], 0.f));
            s = fminf(s, 1.f);
            float th = acosf(s);
            sum += th * th;
        }
        gTheta[bc] = sum;
    }
}

// K4 (grid=Csz): per-channel factor via tree reduction; block 0 also bias Ginv
__global__ void k4_factor(const float* __restrict__ bias, const float* __restrict__ shiftp) {
    __shared__ float red[TB];
    __shared__ double Bb[768], W[256], M1[256], aug[512], fs[18];
    __shared__ int piv;
    const int t = threadIdx.x;
    const int c = blockIdx.x;
    red[t] = gTheta[t * Csz + c] + gTheta[(t + TB) * Csz + c];
    __syncthreads();
    for (int s = TB / 2; s > 0; s >>= 1) {
        if (t < s) red[t] += red[t + s];
        __syncthreads();
    }
    if (t == 0) {
        double var = (double)red[0] * (1.0 / (double)Bsz);
        gFactorF[c] = (float)((double)shiftp[0] / sqrt(var + 1e-5));
    }
    if (c == 0) {
        for (int i = t; i < 768; i += TB) Bb[i] = (double)bias[i];
        __syncthreads();
        gram16d(Bb, W, 48);
        for (int i = t; i < 256; i += TB) {
            int r = i >> 4, cc = i & 15;
            W[i] = 0.25 * W[i] + ((r == cc) ? 1.0 : 0.0);
        }
        __syncthreads();
        invert16d(W, aug, M1, fs, &piv);
        for (int i = t; i < 256; i += TB) gGinvBF[i] = (float)M1[i];
    }
}

// K5 (warp-per-instance): center -> gyro scale -> bias
__global__ void __launch_bounds__(TB) k5_final(const float* __restrict__ X,
                                               const float* __restrict__ bias,
                                               float* __restrict__ out) {
    __shared__ alignas(16) float Xs[WPB][1024];
    __shared__ alignas(16) float Bmw[WPB][768];
    __shared__ alignas(16) float bufa[WPB][512];   // Ginv / W / T1f+Ts
    __shared__ float Vv[WPB][288];
    __shared__ alignas(16) float Tt[WPB][256];
    __shared__ float lamK[WPB][16], sdK[WPB][16], gkK[WPB][16];
    const int w = threadIdx.x >> 5, lane = threadIdx.x & 31;
    const int bc = blockIdx.x * WPB + w;
    const int c = bc & (Csz - 1);
    float* Xw = Xs[w];
    float* Bw = Bmw[w];
    float* buf_f = bufa[w];
    float* V = Vv[w];
    float* T = Tt[w];
    {
        const float4* Xp4 = (const float4*)(X + (size_t)bc * 1024);
        const float4* Bm4 = (const float4*)(gBmF + (size_t)c * 768);
        const float4* Gi4 = (const float4*)(gGinvCF + (size_t)c * 256);
        float4* Xw4 = (float4*)Xw;
        float4* Bw4 = (float4*)Bw;
        float4* bf4 = (float4*)buf_f;
        for (int i = lane; i < 256; i += 32) Xw4[i] = Xp4[i];
        for (int i = lane; i < 192; i += 32) Bw4[i] = Bm4[i];
        for (int i = lane; i < 64; i += 32) bf4[i] = Gi4[i];
    }
    __syncwarp();
    // --- Step A: centering Cayley ---
    for (int i = lane; i < 256; i += 32) {
        int r = i >> 4, cc = i & 15;
        float acc = Xw[i];
        for (int k = 0; k < 48; ++k)
            acc += 0.5f * Bw[k * 16 + r] * Xw[256 + k * 16 + cc];
        T[i] = acc;
    }
    __syncwarp();
    {
        float yreg[8];
        #pragma unroll
        for (int ii = 0; ii < 8; ++ii) {
            int i = lane + 32 * ii, r = i >> 4, cc = i & 15;
            float acc = 0.f;
            #pragma unroll
            for (int x = 0; x < 16; ++x) acc += buf_f[r * 16 + x] * T[x * 16 + cc];
            yreg[ii] = acc;
        }
        __syncwarp();
        #pragma unroll
        for (int ii = 0; ii < 8; ++ii) T[lane + 32 * ii] = yreg[ii];
    }
    __syncwarp();
    for (int i = lane; i < 1024; i += 32) {
        if (i < 256) Xw[i] = 2.f * T[i] - Xw[i];
        else {
            int r = (i - 256) >> 4, cc = i & 15;
            float acc = Xw[i];
            #pragma unroll
            for (int x = 0; x < 16; ++x) acc -= Bw[r * 16 + x] * T[x * 16 + cc];
            Xw[i] = acc;
        }
    }
    __syncwarp();
    // --- Step B: gyro scaling via K = Xu Xu^T ---
    float* W = buf_f;
    for (int i = lane; i < 256; i += 32) {
        int r = i >> 4, cc = i & 15;
        float acc = 0.f;
        #pragma unroll
        for (int x = 0; x < 16; ++x) acc += Xw[r * 16 + x] * Xw[cc * 16 + x];
        W[r * S17 + cc] = acc;
    }
    for (int i = lane; i < 288; i += 32) V[i] = 0.f;
    __syncwarp();
    if (lane < 16) V[lane * S17 + lane] = 1.f;
    jacobi_warp(W, V, lane, SWEEPS_W, true);
    // ---- compensated fp32 T1 (W dead) ----
    float* T1f = buf_f;          // 256
    for (int i = lane; i < 256; i += 32) {
        int r = i >> 4, cc = i & 15;
        float s = 0.f, comp = 0.f;
        #pragma unroll
        for (int x = 0; x < 16; ++x) {
            float a = Xw[x * 16 + r], b = V[x * S17 + cc];
            float p = __fmul_rn(a, b);
            float e = __fmaf_rn(a, b, -p);
            float y = p - comp;
            float t2 = s + y;
            comp = ((t2 - s) - y) - e;
            s = t2;
        }
        T1f[i] = s - comp;
    }
    __syncwarp();
    if (lane < 16) {
        float acc = 0.f;
        #pragma unroll
        for (int r = 0; r < 16; ++r) { float v = T1f[r * 16 + lane]; acc = __fmaf_rn(v, v, acc); }
        lamK[w][lane] = fmaxf(acc, 1e-30f);
    }
    __syncwarp();
    float fct = gFactorF[c];
    if (lane < 16) {
        double lam = (double)lamK[w][lane];
        double om = fmax(1.0 - lam, 0.0);
        double beta, cth;
        if (om < 1e-28) { beta = (double)fct; cth = 1.0; }
        else {
            double th = (double)fct * atan(sqrt(om / lam));
            beta = sin(th) / sqrt(om);
            cth = cos(th);
        }
        sdK[w][lane] = (float)(beta / sqrt(lam));
        gkK[w][lane] = (float)cth;
    }
    __syncwarp();
    // Ts into buf_f+256
    float* Tsf = buf_f + 256;
    for (int i = lane; i < 256; i += 32) Tsf[i] = T1f[i] * sdK[w][i & 15];
    __syncwarp();
    // M2 = Ts V^T and top = V cos V^T, staged in regs, then commit (V -> M2, T -> top)
    {
        float m2reg[8], topreg[8];
        #pragma unroll
        for (int ii = 0; ii < 8; ++ii) {
            int i = lane + 32 * ii, r = i >> 4, cc = i & 15;
            float accm = 0.f, acct = 0.f;
            #pragma unroll
            for (int x = 0; x < 16; ++x) {
                accm += Tsf[r * 16 + x] * V[cc * S17 + x];
                acct += V[r * S17 + x] * gkK[w][x] * V[cc * S17 + x];
            }
            m2reg[ii] = accm;
            topreg[ii] = acct;
        }
        __syncwarp();
        #pragma unroll
        for (int ii = 0; ii < 8; ++ii) {
            V[lane + 32 * ii] = m2reg[ii];
            T[lane + 32 * ii] = topreg[ii];
        }
    }
    __syncwarp();
    // bot = Xl M2 into Bw
    for (int i = lane; i < 768; i += 32) {
        int r = i >> 4, cc = i & 15;
        float acc = 0.f;
        #pragma unroll
        for (int x = 0; x < 16; ++x) acc += Xw[256 + r * 16 + x] * V[x * 16 + cc];
        Bw[i] = acc;
    }
    __syncwarp();
    // commit: Xu=top, Xl=bot
    {
        float4* Xw4 = (float4*)Xw;
        float4* T4 = (float4*)T;
        float4* Bw4 = (float4*)Bw;
        for (int i = lane; i < 64; i += 32) Xw4[i] = T4[i];
        for (int i = lane; i < 192; i += 32) Xw4[64 + i] = Bw4[i];
    }
    __syncwarp();
    // --- Step C: bias Cayley ---
    {
        const float4* b4 = (const float4*)bias;
        const float4* g4 = (const float4*)gGinvBF;
        float4* Bw4 = (float4*)Bw;
        float4* bf4 = (float4*)buf_f;
        for (int i = lane; i < 192; i += 32) Bw4[i] = b4[i];
        for (int i = lane; i < 64; i += 32) bf4[i] = g4[i];
    }
    __syncwarp();
    for (int i = lane; i < 256; i += 32) {
        int r = i >> 4, cc = i & 15;
        float acc = Xw[i];
        for (int k = 0; k < 48; ++k)
            acc -= 0.5f * Bw[k * 16 + r] * Xw[256 + k * 16 + cc];
        T[i] = acc;
    }
    __syncwarp();
    {
        float yreg[8];
        #pragma unroll
        for (int ii = 0; ii < 8; ++ii) {
            int i = lane + 32 * ii, r = i >> 4, cc = i & 15;
            float acc = 0.f;
            #pragma unroll
            for (int x = 0; x < 16; ++x) acc += buf_f[r * 16 + x] * T[x * 16 + cc];
            yreg[ii] = acc;
        }
        __syncwarp();
        #pragma unroll
        for (int ii = 0; ii < 8; ++ii) T[lane + 32 * ii] = yreg[ii];
    }
    __syncwarp();
    float4* dst4 = (float4*)(out + (size_t)bc * 1024);
    for (int i4 = lane; i4 < 64; i4 += 32) {
        float4 t4 = ((float4*)T)[i4];
        float4 x4 = ((float4*)Xw)[i4];
        dst4[i4] = make_float4(2.f * t4.x - x4.x, 2.f * t4.y - x4.y,
                               2.f * t4.z - x4.z, 2.f * t4.w - x4.w);
    }
    for (int i4 = lane; i4 < 192; i4 += 32) {
        int r = i4 >> 2, cb = (i4 & 3) * 4;
        float a0 = Xw[256 + r * 16 + cb];
        float a1 = Xw[256 + r * 16 + cb + 1];
        float a2 = Xw[256 + r * 16 + cb + 2];
        float a3 = Xw[256 + r * 16 + cb + 3];
        #pragma unroll
        for (int x = 0; x < 16; ++x) {
            float bv = Bw[r * 16 + x];
            a0 += bv * T[x * 16 + cb];
            a1 += bv * T[x * 16 + cb + 1];
            a2 += bv * T[x * 16 + cb + 2];
            a3 += bv * T[x * 16 + cb + 3];
        }
        dst4[64 + i4] = make_float4(a0, a1, a2, a3);
    }
}

// ---------------- launch ----------------
extern "C" void kernel_launch(void* const* d_in, const int* in_sizes, int n_in,
                              void* d_out, int out_size) {
    const float* X = (const float*)d_in[0];
    const float* bias = (const float*)d_in[1];
    const float* shift = (const float*)d_in[2];
    float* out = (float*)d_out;
    float* meanOut = out + (size_t)Bsz * Csz * Nsz * Psz;

    const int nInst = Bsz * Csz;
    k1_logmap<<<nInst / WPB, TB>>>(X);
    k2_mean<<<Csz, TB>>>(X, meanOut);
    k3_theta<<<nInst / WPB, TB>>>(X, meanOut);
    k4_factor<<<Csz, TB>>>(bias, shift);
    k5_final<<<nInst / WPB, TB>>>(X, bias, out);
}

// round 11
// speedup vs baseline: 7.8959x; 1.0675x over previous
#include <cuda_runtime.h>

#define Bsz 256
#define Csz 128
#define Nsz 64
#define Psz 16
#define Qsz 48
#define TB 128
#define WPB 4
#define SWEEPS_W 6
#define SWEEPS_NV 4
#define SWEEPS_D 5
#define S17 17

// ---------------- device scratch (static, no allocations) ----------------
__device__ alignas(16) float gXlog[(size_t)Bsz * Csz * Nsz * Psz]; // 128MB
__device__ float gTheta[Bsz * Csz];
__device__ alignas(16) float gBmF[Csz * Qsz * Psz];
__device__ alignas(16) float gGinvCF[Csz * Psz * Psz];
__device__ alignas(16) float gGinvBF[Psz * Psz];
__device__ float gFactorF[Csz];

// ================= warp-level fp32 Jacobi (stride-17 smem) =================
__device__ __forceinline__ void jacobi_warp(float* W, float* V, int lane,
                                            int sweeps, bool wantV) {
    const int j = lane >> 2;
    const int b4 = (lane & 3) * 4;
    for (int sweep = 0; sweep < sweeps; ++sweep) {
        for (int r = 0; r < 15; ++r) {
            int p, q;
            if (j == 0) { p = 15; q = r; }
            else { p = (r + j) % 15; q = (r + 15 - j) % 15; }
            if (p < q) { int tmp = p; p = q; q = tmp; }
            __syncwarp();
            float c = 1.f, s = 0.f;
            if ((lane & 3) == 0) {
                float app = W[p * S17 + p], aqq = W[q * S17 + q], apq = W[p * S17 + q];
                if (fabsf(apq) > 1e-37f) {
                    float tau = (aqq - app) / (2.f * apq);
                    float tt = copysignf(1.f, tau) / (fabsf(tau) + sqrtf(1.f + tau * tau));
                    c = rsqrtf(1.f + tt * tt);
                    s = tt * c;
                }
            }
            c = __shfl_sync(0xffffffffu, c, lane & ~3);
            s = __shfl_sync(0xffffffffu, s, lane & ~3);
            #pragma unroll
            for (int k = 0; k < 4; ++k) {
                int col = b4 + k;
                float wp = W[p * S17 + col], wq = W[q * S17 + col];
                W[p * S17 + col] = c * wp - s * wq;
                W[q * S17 + col] = s * wp + c * wq;
            }
            __syncwarp();
            #pragma unroll
            for (int k = 0; k < 4; ++k) {
                int row = b4 + k;
                float xp = W[row * S17 + p], xq = W[row * S17 + q];
                W[row * S17 + p] = c * xp - s * xq;
                W[row * S17 + q] = s * xp + c * xq;
                if (wantV) {
                    float vp = V[row * S17 + p], vq = V[row * S17 + q];
                    V[row * S17 + p] = c * vp - s * vq;
                    V[row * S17 + q] = s * vp + c * vq;
                }
            }
        }
    }
    __syncwarp();
}

// ================= block-level fp64 helpers (k2) =================
__device__ void jacobi16d(double* W, double* V, double* cs) {
    const int t = threadIdx.x;
    for (int i = t; i < 256; i += TB) V[i] = ((i >> 4) == (i & 15)) ? 1.0 : 0.0;
    __syncthreads();
    const int pr = t >> 4, el = t & 15;
    for (int sweep = 0; sweep < SWEEPS_D; ++sweep) {
        for (int r = 0; r < 15; ++r) {
            int p, q;
            if (pr == 0) { p = 15; q = r; }
            else { p = (r + pr) % 15; q = (r + 15 - pr) % 15; }
            if (p < q) { int tmp = p; p = q; q = tmp; }
            if (el == 0) {
                double app = W[p * 16 + p], aqq = W[q * 16 + q], apq = W[p * 16 + q];
                double c = 1.0, s = 0.0;
                if (fabs(apq) > 1e-300) {
                    double tau = (aqq - app) / (2.0 * apq);
                    double tt = copysign(1.0, tau) / (fabs(tau) + sqrt(1.0 + tau * tau));
                    c = rsqrt(1.0 + tt * tt);
                    s = tt * c;
                }
                cs[pr] = c; cs[8 + pr] = s;
            }
            __syncthreads();
            double c = cs[pr], s = cs[8 + pr];
            double wp = W[p * 16 + el], wq = W[q * 16 + el];
            W[p * 16 + el] = c * wp - s * wq;
            W[q * 16 + el] = s * wp + c * wq;
            __syncthreads();
            double xp = W[el * 16 + p], xq = W[el * 16 + q];
            W[el * 16 + p] = c * xp - s * xq;
            W[el * 16 + q] = s * xp + c * xq;
            double vp = V[el * 16 + p], vq = V[el * 16 + q];
            V[el * 16 + p] = c * vp - s * vq;
            V[el * 16 + q] = s * vp + c * vq;
            __syncthreads();
        }
    }
}

__device__ void invert16d(const double* Min, double* aug, double* Mout, double* fs, int* piv) {
    const int t = threadIdx.x;
    for (int i = t; i < 512; i += TB) {
        int r = i >> 5, cc = i & 31;
        aug[i] = (cc < 16) ? Min[r * 16 + cc] : ((cc - 16 == r) ? 1.0 : 0.0);
    }
    __syncthreads();
    for (int k = 0; k < 16; ++k) {
        if (t == 0) {
            int best = k; double bv = fabs(aug[k * 32 + k]);
            for (int i = k + 1; i < 16; ++i) {
                double v = fabs(aug[i * 32 + k]);
                if (v > bv) { bv = v; best = i; }
            }
            *piv = best;
        }
        __syncthreads();
        int pb = *piv;
        if (pb != k && t < 32) {
            double tmp = aug[k * 32 + t];
            aug[k * 32 + t] = aug[pb * 32 + t];
            aug[pb * 32 + t] = tmp;
        }
        __syncthreads();
        if (t == 0) fs[16] = 1.0 / aug[k * 32 + k];
        __syncthreads();
        if (t < 32) aug[k * 32 + t] *= fs[16];
        __syncthreads();
        if (t < 16) fs[t] = aug[t * 32 + k];
        __syncthreads();
        for (int i = t; i < 512; i += TB) {
            int r = i >> 5, cc = i & 31;
            if (r != k) aug[i] -= fs[r] * aug[k * 32 + cc];
        }
        __syncthreads();
    }
    for (int i = t; i < 256; i += TB) Mout[i] = aug[(i >> 4) * 32 + 16 + (i & 15)];
    __syncthreads();
}

__device__ void matmul16d(const double* A, const double* Bm, double* Cc, int m) {
    const int t = threadIdx.x;
    for (int i = t; i < m * 16; i += TB) {
        int r = i >> 4, cc = i & 15;
        double acc = 0.0;
        #pragma unroll
        for (int x = 0; x < 16; ++x) acc += A[r * 16 + x] * Bm[x * 16 + cc];
        Cc[i] = acc;
    }
    __syncthreads();
}

__device__ void gram16d(const double* A, double* W, int m) {
    const int t = threadIdx.x;
    for (int i = t; i < 256; i += TB) {
        int r = i >> 4, cc = i & 15;
        double acc = 0.0;
        for (int x = 0; x < m; ++x) acc += A[x * 16 + r] * A[x * 16 + cc];
        W[i] = acc;
    }
    __syncthreads();
}

__device__ void vdvtd(const double* V, const double* g, double* P) {
    const int t = threadIdx.x;
    for (int i = t; i < 256; i += TB) {
        int r = i >> 4, cc = i & 15;
        double acc = 0.0;
        #pragma unroll
        for (int x = 0; x < 16; ++x) acc += V[r * 16 + x] * g[x] * V[cc * 16 + x];
        P[i] = acc;
    }
    __syncthreads();
}

// ================= kernels =================

// K1 (warp-per-instance): x_log = log_map(X[0,c], X[b,c]) -> gXlog[bc]
// smem overlay: Ub holds U until Z is formed; then W/V/T1f/lam/sd live in it.
__global__ void __launch_bounds__(TB) k1_logmap(const float* __restrict__ X) {
    __shared__ alignas(16) float Ub[WPB][1024];
    __shared__ alignas(16) float Zb[WPB][1024];
    __shared__ float Mm[WPB][272];
    const int w = threadIdx.x >> 5, lane = threadIdx.x & 31;
    const int bc = blockIdx.x * WPB + w;
    const int c = bc & (Csz - 1);
    float* U = Ub[w];
    float* Z = Zb[w];
    float* M = Mm[w];
    // overlay pointers (valid after U is dead)
    float* W    = Ub[w];          // 288 (stride-17 16x16)
    float* V    = Ub[w] + 288;    // 288
    float* T1f  = Ub[w] + 576;    // 256
    float* lamA = Ub[w] + 832;    // 16
    float* sdA  = Ub[w] + 848;    // 16
    const float4* Xp4 = (const float4*)(X + (size_t)bc * 1024);
    const float4* Up4 = (const float4*)(X + (size_t)c * 1024);
    float4* U4 = (float4*)U;
    float4* Z4 = (float4*)Z;
    for (int i = lane; i < 256; i += 32) { U4[i] = Up4[i]; Z4[i] = Xp4[i]; }
    __syncwarp();
    // M = U^T X
    for (int i = lane; i < 256; i += 32) {
        int r = i >> 4, cc = i & 15;
        float acc = 0.f;
        for (int x = 0; x < 64; ++x) acc += U[x * 16 + r] * Z[x * 16 + cc];
        M[r * S17 + cc] = acc;
    }
    __syncwarp();
    // Z = Z - U M  (last use of U)
    for (int i = lane; i < 1024; i += 32) {
        int r = i >> 4, cc = i & 15;
        float acc = Z[i];
        #pragma unroll
        for (int x = 0; x < 16; ++x) acc -= U[r * 16 + x] * M[x * S17 + cc];
        Z[i] = acc;
    }
    __syncwarp();
    // W = M M^T (bounded) into overlay
    for (int i = lane; i < 256; i += 32) {
        int r = i >> 4, cc = i & 15;
        float acc = 0.f;
        #pragma unroll
        for (int x = 0; x < 16; ++x) acc += M[r * S17 + x] * M[cc * S17 + x];
        W[r * S17 + cc] = acc;
    }
    for (int i = lane; i < 288; i += 32) V[i] = 0.f;
    __syncwarp();
    if (lane < 16) V[lane * S17 + lane] = 1.f;
    jacobi_warp(W, V, lane, SWEEPS_W, true);
    // T1 = M^T V (Kahan+TwoProd fp32)
    for (int i = lane; i < 256; i += 32) {
        int r = i >> 4, cc = i & 15;
        float s = 0.f, comp = 0.f;
        #pragma unroll
        for (int x = 0; x < 16; ++x) {
            float a = M[x * S17 + r], b = V[x * S17 + cc];
            float p = __fmul_rn(a, b);
            float e = __fmaf_rn(a, b, -p);
            float y = p - comp;
            float t2 = s + y;
            comp = ((t2 - s) - y) - e;
            s = t2;
        }
        T1f[i] = s - comp;
    }
    __syncwarp();
    if (lane < 16) {
        float acc = 0.f;
        #pragma unroll
        for (int r = 0; r < 16; ++r) { float v = T1f[r * 16 + lane]; acc = __fmaf_rn(v, v, acc); }
        lamA[lane] = fmaxf(acc, 1e-30f);
    }
    __syncwarp();
    if (lane < 16) {
        double lam = (double)lamA[lane];
        double om = fmax(1.0 - lam, 0.0);
        double alpha = (om < 1e-28) ? 1.0 : atan(sqrt(om / lam)) / sqrt(om);
        sdA[lane] = (float)(alpha / sqrt(lam));
    }
    __syncwarp();
    // Ts into M (bounded); M's last read was T1 above
    for (int i = lane; i < 256; i += 32)
        M[(i >> 4) * S17 + (i & 15)] = T1f[i] * sdA[i & 15];
    __syncwarp();
    // G = Ts V^T into W slot (W dead)
    for (int i = lane; i < 256; i += 32) {
        int r = i >> 4, cc = i & 15;
        float acc = 0.f;
        #pragma unroll
        for (int x = 0; x < 16; ++x) acc += M[r * S17 + x] * V[cc * S17 + x];
        W[r * S17 + cc] = acc;
    }
    __syncwarp();
    // x_log = Z G -> gXlog
    float4* dst4 = (float4*)(gXlog + (size_t)bc * 1024);
    for (int i4 = lane; i4 < 256; i4 += 32) {
        int r = i4 >> 2, cb = (i4 & 3) * 4;
        float a0 = 0.f, a1 = 0.f, a2 = 0.f, a3 = 0.f;
        #pragma unroll
        for (int x = 0; x < 16; ++x) {
            float z = Z[r * 16 + x];
            a0 += z * W[x * S17 + cb];
            a1 += z * W[x * S17 + cb + 1];
            a2 += z * W[x * S17 + cb + 2];
            a3 += z * W[x * S17 + cb + 3];
        }
        dst4[i4] = make_float4(a0, a1, a2, a3);
    }
}

// K2 (grid=Csz+1): blocks 0..127 per-channel mean/Bm/GinvC; block 128 bias GinvB.
__global__ void k2_mean(const float* __restrict__ X, float* __restrict__ meanOut,
                        const float* __restrict__ bias) {
    __shared__ double Dm[1024], U0[1024], meanS[1024], Cm[768];
    __shared__ double W[256], V[256], M1[256], M2[256], aug[512];
    __shared__ double g[32], cs[16], fs[18];
    __shared__ int piv;
    const int c = blockIdx.x;
    const int t = threadIdx.x;
    if (c == Csz) {
        // bias Cayley GinvB (runs concurrently with the channel blocks)
        for (int i = t; i < 768; i += TB) Cm[i] = (double)bias[i];
        __syncthreads();
        gram16d(Cm, W, 48);
        for (int i = t; i < 256; i += TB) {
            int r = i >> 4, cc = i & 15;
            W[i] = 0.25 * W[i] + ((r == cc) ? 1.0 : 0.0);
        }
        __syncthreads();
        invert16d(W, aug, M1, fs, &piv);
        for (int i = t; i < 256; i += TB) gGinvBF[i] = (float)M1[i];
        return;
    }
    const float4* gX4 = (const float4*)gXlog;
    for (int i4 = t; i4 < 256; i4 += TB) {
        float a0 = 0.f, a1 = 0.f, a2 = 0.f, a3 = 0.f;
        #pragma unroll 4
        for (int b = 0; b < Bsz; ++b) {
            float4 v = gX4[((size_t)b * Csz + c) * 256 + i4];
            a0 += v.x; a1 += v.y; a2 += v.z; a3 += v.w;
        }
        const double inv = 1.0 / (double)Bsz;
        int i = i4 * 4;
        Dm[i] = (double)a0 * inv; Dm[i + 1] = (double)a1 * inv;
        Dm[i + 2] = (double)a2 * inv; Dm[i + 3] = (double)a3 * inv;
    }
    for (int i = t; i < 1024; i += TB)
        U0[i] = (double)X[(size_t)c * 1024 + i];
    __syncthreads();
    gram16d(Dm, W, 64);
    jacobi16d(W, V, cs);
    if (t < 16) {
        double S = sqrt(fmax(W[t * 17], 0.0));
        g[t] = cos(S);
        g[16 + t] = (S > 1e-100) ? sin(S) / S : 1.0;
    }
    __syncthreads();
    vdvtd(V, g, M1);
    vdvtd(V, g + 16, M2);
    for (int i = t; i < 1024; i += TB) {
        int r = i >> 4, cc = i & 15;
        double acc = 0.0;
        #pragma unroll
        for (int x = 0; x < 16; ++x)
            acc += U0[r * 16 + x] * M1[x * 16 + cc] + Dm[r * 16 + x] * M2[x * 16 + cc];
        meanS[i] = acc;
        meanOut[c * 1024 + i] = (float)acc;
    }
    __syncthreads();
    invert16d(meanS, aug, M1, fs, &piv);
    matmul16d(meanS + 256, M1, Cm, 48);
    gram16d(Cm, W, 48);
    jacobi16d(W, V, cs);
    if (t < 16) {
        double S = sqrt(fmax(W[t * 17], 0.0));
        g[t] = (S > 1e-100) ? atan(S) / S : 1.0;
    }
    __syncthreads();
    vdvtd(V, g, M2);
    matmul16d(Cm, M2, Dm, 48);
    for (int i = t; i < 768; i += TB) gBmF[c * 768 + i] = (float)Dm[i];
    __syncthreads();
    gram16d(Dm, W, 48);
    for (int i = t; i < 256; i += TB) {
        int r = i >> 4, cc = i & 15;
        W[i] = 0.25 * W[i] + ((r == cc) ? 1.0 : 0.0);
    }
    __syncthreads();
    invert16d(W, aug, M1, fs, &piv);
    for (int i = t; i < 256; i += TB) gGinvCF[c * 256 + i] = (float)M1[i];
}

// K3 (warp-per-instance): theta^2 sum -> gTheta[bc]
// smem overlay: Mn holds mean until M computed; then W lives in it.
__global__ void __launch_bounds__(TB) k3_theta(const float* __restrict__ X,
                                               const float* __restrict__ meanIn) {
    __shared__ alignas(16) float Mn[WPB][1024];
    __shared__ alignas(16) float Xb[WPB][1024];
    __shared__ float Mm[WPB][272];
    const int w = threadIdx.x >> 5, lane = threadIdx.x & 31;
    const int bc = blockIdx.x * WPB + w;
    const int c = bc & (Csz - 1);
    float* A = Mn[w];
    float* Xl = Xb[w];
    float* M = Mm[w];
    float* W = Mn[w];              // overlay (mean dead after M computed)
    const float4* Xp4 = (const float4*)(X + (size_t)bc * 1024);
    const float4* Mp4 = (const float4*)(meanIn + (size_t)c * 1024);
    float4* A4 = (float4*)A;
    float4* Xl4 = (float4*)Xl;
    for (int i = lane; i < 256; i += 32) { A4[i] = Mp4[i]; Xl4[i] = Xp4[i]; }
    __syncwarp();
    for (int i = lane; i < 256; i += 32) {
        int r = i >> 4, cc = i & 15;
        float acc = 0.f;
        for (int x = 0; x < 64; ++x) acc += A[x * 16 + r] * Xl[x * 16 + cc];
        M[r * S17 + cc] = acc;
    }
    __syncwarp();
    for (int i = lane; i < 256; i += 32) {
        int r = i >> 4, cc = i & 15;
        float acc = 0.f;
        #pragma unroll
        for (int x = 0; x < 16; ++x) acc += M[x * S17 + r] * M[x * S17 + cc];
        W[r * S17 + cc] = acc;
    }
    __syncwarp();
    jacobi_warp(W, (float*)0, lane, SWEEPS_NV, false);
    if (lane == 0) {
        float sum = 0.f;
        for (int j2 = 0; j2 < 16; ++j2) {
            float s = sqrtf(fmaxf(W[j2 * 18], 0.f));
            s = fminf(s, 1.f);
            float th = acosf(s);
            sum += th * th;
        }
        gTheta[bc] = sum;
    }
}

// K4 (grid=Csz): per-channel factor via tree reduction only
__global__ void k4_factor(const float* __restrict__ shiftp) {
    __shared__ float red[TB];
    const int t = threadIdx.x;
    const int c = blockIdx.x;
    red[t] = gTheta[t * Csz + c] + gTheta[(t + TB) * Csz + c];
    __syncthreads();
    for (int s = TB / 2; s > 0; s >>= 1) {
        if (t < s) red[t] += red[t + s];
        __syncthreads();
    }
    if (t == 0) {
        double var = (double)red[0] * (1.0 / (double)Bsz);
        gFactorF[c] = (float)((double)shiftp[0] / sqrt(var + 1e-5));
    }
}

// K5 (warp-per-instance): center -> gyro scale -> bias
// smem overlay: V lives in Bmw after Bm dead; M2 reuses T1f slot in bufa.
__global__ void __launch_bounds__(TB) k5_final(const float* __restrict__ X,
                                               const float* __restrict__ bias,
                                               float* __restrict__ out) {
    __shared__ alignas(16) float Xs[WPB][1024];
    __shared__ alignas(16) float Bmw[WPB][768];   // Bm -> V -> bot -> bias
    __shared__ alignas(16) float bufa[WPB][512];  // Ginv/W -> T1f,Tsf -> M2 / GinvB
    __shared__ alignas(16) float Tt[WPB][256];    // T (A) -> top -> T (C)
    __shared__ float lamK[WPB][16], sdK[WPB][16], gkK[WPB][16];
    const int w = threadIdx.x >> 5, lane = threadIdx.x & 31;
    const int bc = blockIdx.x * WPB + w;
    const int c = bc & (Csz - 1);
    float* Xw = Xs[w];
    float* Bw = Bmw[w];
    float* buf_f = bufa[w];
    float* T = Tt[w];
    {
        const float4* Xp4 = (const float4*)(X + (size_t)bc * 1024);
        const float4* Bm4 = (const float4*)(gBmF + (size_t)c * 768);
        const float4* Gi4 = (const float4*)(gGinvCF + (size_t)c * 256);
        float4* Xw4 = (float4*)Xw;
        float4* Bw4 = (float4*)Bw;
        float4* bf4 = (float4*)buf_f;
        for (int i = lane; i < 256; i += 32) Xw4[i] = Xp4[i];
        for (int i = lane; i < 192; i += 32) Bw4[i] = Bm4[i];
        for (int i = lane; i < 64; i += 32) bf4[i] = Gi4[i];
    }
    __syncwarp();
    // --- Step A: centering Cayley ---
    for (int i = lane; i < 256; i += 32) {
        int r = i >> 4, cc = i & 15;
        float acc = Xw[i];
        for (int k = 0; k < 48; ++k)
            acc += 0.5f * Bw[k * 16 + r] * Xw[256 + k * 16 + cc];
        T[i] = acc;
    }
    __syncwarp();
    {
        float yreg[8];
        #pragma unroll
        for (int ii = 0; ii < 8; ++ii) {
            int i = lane + 32 * ii, r = i >> 4, cc = i & 15;
            float acc = 0.f;
            #pragma unroll
            for (int x = 0; x < 16; ++x) acc += buf_f[r * 16 + x] * T[x * 16 + cc];
            yreg[ii] = acc;
        }
        __syncwarp();
        #pragma unroll
        for (int ii = 0; ii < 8; ++ii) T[lane + 32 * ii] = yreg[ii];
    }
    __syncwarp();
    for (int i = lane; i < 1024; i += 32) {
        if (i < 256) Xw[i] = 2.f * T[i] - Xw[i];
        else {
            int r = (i - 256) >> 4, cc = i & 15;
            float acc = Xw[i];
            #pragma unroll
            for (int x = 0; x < 16; ++x) acc -= Bw[r * 16 + x] * T[x * 16 + cc];
            Xw[i] = acc;                       // last use of Bm
        }
    }
    __syncwarp();
    // --- Step B: gyro scaling via K = Xu Xu^T ---
    float* W = buf_f;                          // Ginv dead
    float* V = Bw;                             // Bm dead; V stride-17 in Bmw[0..287]
    for (int i = lane; i < 256; i += 32) {
        int r = i >> 4, cc = i & 15;
        float acc = 0.f;
        #pragma unroll
        for (int x = 0; x < 16; ++x) acc += Xw[r * 16 + x] * Xw[cc * 16 + x];
        W[r * S17 + cc] = acc;
    }
    for (int i = lane; i < 288; i += 32) V[i] = 0.f;
    __syncwarp();
    if (lane < 16) V[lane * S17 + lane] = 1.f;
    jacobi_warp(W, V, lane, SWEEPS_W, true);
    // ---- compensated fp32 T1 (W dead) ----
    float* T1f = buf_f;          // 256
    for (int i = lane; i < 256; i += 32) {
        int r = i >> 4, cc = i & 15;
        float s = 0.f, comp = 0.f;
        #pragma unroll
        for (int x = 0; x < 16; ++x) {
            float a = Xw[x * 16 + r], b = V[x * S17 + cc];
            float p = __fmul_rn(a, b);
            float e = __fmaf_rn(a, b, -p);
            float y = p - comp;
            float t2 = s + y;
            comp = ((t2 - s) - y) - e;
            s = t2;
        }
        T1f[i] = s - comp;
    }
    __syncwarp();
    if (lane < 16) {
        float acc = 0.f;
        #pragma unroll
        for (int r = 0; r < 16; ++r) { float v = T1f[r * 16 + lane]; acc = __fmaf_rn(v, v, acc); }
        lamK[w][lane] = fmaxf(acc, 1e-30f);
    }
    __syncwarp();
    float fct = gFactorF[c];
    if (lane < 16) {
        double lam = (double)lamK[w][lane];
        double om = fmax(1.0 - lam, 0.0);
        double beta, cth;
        if (om < 1e-28) { beta = (double)fct; cth = 1.0; }
        else {
            double th = (double)fct * atan(sqrt(om / lam));
            beta = sin(th) / sqrt(om);
            cth = cos(th);
        }
        sdK[w][lane] = (float)(beta / sqrt(lam));
        gkK[w][lane] = (float)cth;
    }
    __syncwarp();
    // Ts into buf_f+256
    float* Tsf = buf_f + 256;
    for (int i = lane; i < 256; i += 32) Tsf[i] = T1f[i] * sdK[w][i & 15];
    __syncwarp();
    // M2 = Ts V^T and top = V cos V^T, staged; commit M2 -> buf_f[0..255] (T1f dead), top -> T
    {
        float m2reg[8], topreg[8];
        #pragma unroll
        for (int ii = 0; ii < 8; ++ii) {
            int i = lane + 32 * ii, r = i >> 4, cc = i & 15;
            float accm = 0.f, acct = 0.f;
            #pragma unroll
            for (int x = 0; x < 16; ++x) {
                accm += Tsf[r * 16 + x] * V[cc * S17 + x];
                acct += V[r * S17 + x] * gkK[w][x] * V[cc * S17 + x];
            }
            m2reg[ii] = accm;
            topreg[ii] = acct;
        }
        __syncwarp();
        #pragma unroll
        for (int ii = 0; ii < 8; ++ii) {
            buf_f[lane + 32 * ii] = m2reg[ii];   // M2
            T[lane + 32 * ii] = topreg[ii];      // top
        }
    }
    __syncwarp();
    // bot = Xl M2 into Bw (V dead)
    for (int i = lane; i < 768; i += 32) {
        int r = i >> 4, cc = i & 15;
        float acc = 0.f;
        #pragma unroll
        for (int x = 0; x < 16; ++x) acc += Xw[256 + r * 16 + x] * buf_f[x * 16 + cc];
        Bw[i] = acc;
    }
    __syncwarp();
    // commit: Xu=top, Xl=bot
    {
        float4* Xw4 = (float4*)Xw;
        float4* T4 = (float4*)T;
        float4* Bw4 = (float4*)Bw;
        for (int i = lane; i < 64; i += 32) Xw4[i] = T4[i];
        for (int i = lane; i < 192; i += 32) Xw4[64 + i] = Bw4[i];
    }
    __syncwarp();
    // --- Step C: bias Cayley ---
    {
        const float4* b4 = (const float4*)bias;
        const float4* g4 = (const float4*)gGinvBF;
        float4* Bw4 = (float4*)Bw;
        float4* bf4 = (float4*)buf_f;
        for (int i = lane; i < 192; i += 32) Bw4[i] = b4[i];
        for (int i = lane; i < 64; i += 32) bf4[i] = g4[i];
    }
    __syncwarp();
    for (int i = lane; i < 256; i += 32) {
        int r = i >> 4, cc = i & 15;
        float acc = Xw[i];
        for (int k = 0; k < 48; ++k)
            acc -= 0.5f * Bw[k * 16 + r] * Xw[256 + k * 16 + cc];
        T[i] = acc;
    }
    __syncwarp();
    {
        float yreg[8];
        #pragma unroll
        for (int ii = 0; ii < 8; ++ii) {
            int i = lane + 32 * ii, r = i >> 4, cc = i & 15;
            float acc = 0.f;
            #pragma unroll
            for (int x = 0; x < 16; ++x) acc += buf_f[r * 16 + x] * T[x * 16 + cc];
            yreg[ii] = acc;
        }
        __syncwarp();
        #pragma unroll
        for (int ii = 0; ii < 8; ++ii) T[lane + 32 * ii] = yreg[ii];
    }
    __syncwarp();
    float4* dst4 = (float4*)(out + (size_t)bc * 1024);
    for (int i4 = lane; i4 < 64; i4 += 32) {
        float4 t4 = ((float4*)T)[i4];
        float4 x4 = ((float4*)Xw)[i4];
        dst4[i4] = make_float4(2.f * t4.x - x4.x, 2.f * t4.y - x4.y,
                               2.f * t4.z - x4.z, 2.f * t4.w - x4.w);
    }
    for (int i4 = lane; i4 < 192; i4 += 32) {
        int r = i4 >> 2, cb = (i4 & 3) * 4;
        float a0 = Xw[256 + r * 16 + cb];
        float a1 = Xw[256 + r * 16 + cb + 1];
        float a2 = Xw[256 + r * 16 + cb + 2];
        float a3 = Xw[256 + r * 16 + cb + 3];
        #pragma unroll
        for (int x = 0; x < 16; ++x) {
            float bv = Bw[r * 16 + x];
            a0 += bv * T[x * 16 + cb];
            a1 += bv * T[x * 16 + cb + 1];
            a2 += bv * T[x * 16 + cb + 2];
            a3 += bv * T[x * 16 + cb + 3];
        }
        dst4[64 + i4] = make_float4(a0, a1, a2, a3);
    }
}

// ---------------- launch ----------------
extern "C" void kernel_launch(void* const* d_in, const int* in_sizes, int n_in,
                              void* d_out, int out_size) {
    const float* X = (const float*)d_in[0];
    const float* bias = (const float*)d_in[1];
    const float* shift = (const float*)d_in[2];
    float* out = (float*)d_out;
    float* meanOut = out + (size_t)Bsz * Csz * Nsz * Psz;

    const int nInst = Bsz * Csz;
    k1_logmap<<<nInst / WPB, TB>>>(X);
    k2_mean<<<Csz + 1, TB>>>(X, meanOut, bias);
    k3_theta<<<nInst / WPB, TB>>>(X, meanOut);
    k4_factor<<<Csz, TB>>>(shift);
    k5_final<<<nInst / WPB, TB>>>(X, bias, out);
}

// round 12
// speedup vs baseline: 8.3284x; 1.0548x over previous
#include <cuda_runtime.h>

#define Bsz 256
#define Csz 128
#define Nsz 64
#define Psz 16
#define Qsz 48
#define TB 128
#define WPB 4
#define SWEEPS_W 6
#define SWEEPS_NV 4
#define SWEEPS_D 5
#define S17 17
#define JTOL 1e-13f

// ---------------- device scratch (static, no allocations) ----------------
__device__ alignas(16) float gXlog[(size_t)Bsz * Csz * Nsz * Psz]; // 128MB
__device__ float gTheta[Bsz * Csz];
__device__ alignas(16) float gBmF[Csz * Qsz * Psz];
__device__ alignas(16) float gGinvCF[Csz * Psz * Psz];
__device__ alignas(16) float gGinvBF[Psz * Psz];
__device__ float gFactorF[Csz];

// ================= warp-level fp32 Jacobi (stride-17 smem, early exit) =================
__device__ __forceinline__ void jacobi_warp(float* W, float* V, int lane,
                                            int sweeps, bool wantV) {
    const int j = lane >> 2;
    const int b4 = (lane & 3) * 4;
    for (int sweep = 0; sweep < sweeps; ++sweep) {
        if (sweep >= sweeps - 2) {
            // convergence probe: off-diagonal Frobenius^2
            float acc = 0.f;
            #pragma unroll
            for (int ii = 0; ii < 8; ++ii) {
                int i = lane + 32 * ii;
                int r = i >> 4, cc = i & 15;
                float v = (r < cc) ? W[r * S17 + cc] : 0.f;
                acc = __fmaf_rn(v, v, acc);
            }
            #pragma unroll
            for (int off = 16; off; off >>= 1)
                acc += __shfl_xor_sync(0xffffffffu, acc, off);
            if (acc < JTOL) break;
        }
        for (int r = 0; r < 15; ++r) {
            int p, q;
            if (j == 0) { p = 15; q = r; }
            else { p = (r + j) % 15; q = (r + 15 - j) % 15; }
            if (p < q) { int tmp = p; p = q; q = tmp; }
            __syncwarp();
            float c = 1.f, s = 0.f;
            if ((lane & 3) == 0) {
                float app = W[p * S17 + p], aqq = W[q * S17 + q], apq = W[p * S17 + q];
                if (fabsf(apq) > 1e-37f) {
                    float tau = (aqq - app) / (2.f * apq);
                    float tt = copysignf(1.f, tau) / (fabsf(tau) + sqrtf(1.f + tau * tau));
                    c = rsqrtf(1.f + tt * tt);
                    s = tt * c;
                }
            }
            c = __shfl_sync(0xffffffffu, c, lane & ~3);
            s = __shfl_sync(0xffffffffu, s, lane & ~3);
            #pragma unroll
            for (int k = 0; k < 4; ++k) {
                int col = b4 + k;
                float wp = W[p * S17 + col], wq = W[q * S17 + col];
                W[p * S17 + col] = c * wp - s * wq;
                W[q * S17 + col] = s * wp + c * wq;
            }
            __syncwarp();
            #pragma unroll
            for (int k = 0; k < 4; ++k) {
                int row = b4 + k;
                float xp = W[row * S17 + p], xq = W[row * S17 + q];
                W[row * S17 + p] = c * xp - s * xq;
                W[row * S17 + q] = s * xp + c * xq;
                if (wantV) {
                    float vp = V[row * S17 + p], vq = V[row * S17 + q];
                    V[row * S17 + p] = c * vp - s * vq;
                    V[row * S17 + q] = s * vp + c * vq;
                }
            }
        }
    }
    __syncwarp();
}

// ================= block-level fp64 helpers (k2) =================
__device__ void jacobi16d(double* W, double* V, double* cs) {
    const int t = threadIdx.x;
    for (int i = t; i < 256; i += TB) V[i] = ((i >> 4) == (i & 15)) ? 1.0 : 0.0;
    __syncthreads();
    const int pr = t >> 4, el = t & 15;
    for (int sweep = 0; sweep < SWEEPS_D; ++sweep) {
        for (int r = 0; r < 15; ++r) {
            int p, q;
            if (pr == 0) { p = 15; q = r; }
            else { p = (r + pr) % 15; q = (r + 15 - pr) % 15; }
            if (p < q) { int tmp = p; p = q; q = tmp; }
            if (el == 0) {
                double app = W[p * 16 + p], aqq = W[q * 16 + q], apq = W[p * 16 + q];
                double c = 1.0, s = 0.0;
                if (fabs(apq) > 1e-300) {
                    double tau = (aqq - app) / (2.0 * apq);
                    double tt = copysign(1.0, tau) / (fabs(tau) + sqrt(1.0 + tau * tau));
                    c = rsqrt(1.0 + tt * tt);
                    s = tt * c;
                }
                cs[pr] = c; cs[8 + pr] = s;
            }
            __syncthreads();
            double c = cs[pr], s = cs[8 + pr];
            double wp = W[p * 16 + el], wq = W[q * 16 + el];
            W[p * 16 + el] = c * wp - s * wq;
            W[q * 16 + el] = s * wp + c * wq;
            __syncthreads();
            double xp = W[el * 16 + p], xq = W[el * 16 + q];
            W[el * 16 + p] = c * xp - s * xq;
            W[el * 16 + q] = s * xp + c * xq;
            double vp = V[el * 16 + p], vq = V[el * 16 + q];
            V[el * 16 + p] = c * vp - s * vq;
            V[el * 16 + q] = s * vp + c * vq;
            __syncthreads();
        }
    }
}

__device__ void invert16d(const double* Min, double* aug, double* Mout, double* fs, int* piv) {
    const int t = threadIdx.x;
    for (int i = t; i < 512; i += TB) {
        int r = i >> 5, cc = i & 31;
        aug[i] = (cc < 16) ? Min[r * 16 + cc] : ((cc - 16 == r) ? 1.0 : 0.0);
    }
    __syncthreads();
    for (int k = 0; k < 16; ++k) {
        if (t == 0) {
            int best = k; double bv = fabs(aug[k * 32 + k]);
            for (int i = k + 1; i < 16; ++i) {
                double v = fabs(aug[i * 32 + k]);
                if (v > bv) { bv = v; best = i; }
            }
            *piv = best;
        }
        __syncthreads();
        int pb = *piv;
        if (pb != k && t < 32) {
            double tmp = aug[k * 32 + t];
            aug[k * 32 + t] = aug[pb * 32 + t];
            aug[pb * 32 + t] = tmp;
        }
        __syncthreads();
        if (t == 0) fs[16] = 1.0 / aug[k * 32 + k];
        __syncthreads();
        if (t < 32) aug[k * 32 + t] *= fs[16];
        __syncthreads();
        if (t < 16) fs[t] = aug[t * 32 + k];
        __syncthreads();
        for (int i = t; i < 512; i += TB) {
            int r = i >> 5, cc = i & 31;
            if (r != k) aug[i] -= fs[r] * aug[k * 32 + cc];
        }
        __syncthreads();
    }
    for (int i = t; i < 256; i += TB) Mout[i] = aug[(i >> 4) * 32 + 16 + (i & 15)];
    __syncthreads();
}

__device__ void matmul16d(const double* A, const double* Bm, double* Cc, int m) {
    const int t = threadIdx.x;
    for (int i = t; i < m * 16; i += TB) {
        int r = i >> 4, cc = i & 15;
        double acc = 0.0;
        #pragma unroll
        for (int x = 0; x < 16; ++x) acc += A[r * 16 + x] * Bm[x * 16 + cc];
        Cc[i] = acc;
    }
    __syncthreads();
}

__device__ void gram16d(const double* A, double* W, int m) {
    const int t = threadIdx.x;
    for (int i = t; i < 256; i += TB) {
        int r = i >> 4, cc = i & 15;
        double acc = 0.0;
        for (int x = 0; x < m; ++x) acc += A[x * 16 + r] * A[x * 16 + cc];
        W[i] = acc;
    }
    __syncthreads();
}

__device__ void vdvtd(const double* V, const double* g, double* P) {
    const int t = threadIdx.x;
    for (int i = t; i < 256; i += TB) {
        int r = i >> 4, cc = i & 15;
        double acc = 0.0;
        #pragma unroll
        for (int x = 0; x < 16; ++x) acc += V[r * 16 + x] * g[x] * V[cc * 16 + x];
        P[i] = acc;
    }
    __syncthreads();
}

// ================= kernels =================

// K1 (warp-per-instance): x_log = log_map(X[0,c], X[b,c]) -> gXlog[bc]
__global__ void __launch_bounds__(TB) k1_logmap(const float* __restrict__ X) {
    __shared__ alignas(16) float Ub[WPB][1024];
    __shared__ alignas(16) float Zb[WPB][1024];
    __shared__ float Mm[WPB][272];
    const int w = threadIdx.x >> 5, lane = threadIdx.x & 31;
    const int bc = blockIdx.x * WPB + w;
    const int c = bc & (Csz - 1);
    float* U = Ub[w];
    float* Z = Zb[w];
    float* M = Mm[w];
    // overlay pointers (valid after U is dead)
    float* W    = Ub[w];          // 288 (stride-17 16x16)
    float* V    = Ub[w] + 288;    // 288
    float* T1f  = Ub[w] + 576;    // 256
    float* lamA = Ub[w] + 832;    // 16
    float* sdA  = Ub[w] + 848;    // 16
    const float4* Xp4 = (const float4*)(X + (size_t)bc * 1024);
    const float4* Up4 = (const float4*)(X + (size_t)c * 1024);
    float4* U4 = (float4*)U;
    float4* Z4 = (float4*)Z;
    for (int i = lane; i < 256; i += 32) { U4[i] = Up4[i]; Z4[i] = Xp4[i]; }
    __syncwarp();
    // M = U^T X
    for (int i = lane; i < 256; i += 32) {
        int r = i >> 4, cc = i & 15;
        float acc = 0.f;
        for (int x = 0; x < 64; ++x) acc += U[x * 16 + r] * Z[x * 16 + cc];
        M[r * S17 + cc] = acc;
    }
    __syncwarp();
    // Z = Z - U M  (last use of U)
    for (int i = lane; i < 1024; i += 32) {
        int r = i >> 4, cc = i & 15;
        float acc = Z[i];
        #pragma unroll
        for (int x = 0; x < 16; ++x) acc -= U[r * 16 + x] * M[x * S17 + cc];
        Z[i] = acc;
    }
    __syncwarp();
    // W = M M^T (bounded) into overlay
    for (int i = lane; i < 256; i += 32) {
        int r = i >> 4, cc = i & 15;
        float acc = 0.f;
        #pragma unroll
        for (int x = 0; x < 16; ++x) acc += M[r * S17 + x] * M[cc * S17 + x];
        W[r * S17 + cc] = acc;
    }
    for (int i = lane; i < 288; i += 32) V[i] = 0.f;
    __syncwarp();
    if (lane < 16) V[lane * S17 + lane] = 1.f;
    jacobi_warp(W, V, lane, SWEEPS_W, true);
    // T1 = M^T V (Kahan+TwoProd fp32)
    for (int i = lane; i < 256; i += 32) {
        int r = i >> 4, cc = i & 15;
        float s = 0.f, comp = 0.f;
        #pragma unroll
        for (int x = 0; x < 16; ++x) {
            float a = M[x * S17 + r], b = V[x * S17 + cc];
            float p = __fmul_rn(a, b);
            float e = __fmaf_rn(a, b, -p);
            float y = p - comp;
            float t2 = s + y;
            comp = ((t2 - s) - y) - e;
            s = t2;
        }
        T1f[i] = s - comp;
    }
    __syncwarp();
    if (lane < 16) {
        float acc = 0.f;
        #pragma unroll
        for (int r = 0; r < 16; ++r) { float v = T1f[r * 16 + lane]; acc = __fmaf_rn(v, v, acc); }
        lamA[lane] = fmaxf(acc, 1e-30f);
    }
    __syncwarp();
    if (lane < 16) {
        double lam = (double)lamA[lane];
        double om = fmax(1.0 - lam, 0.0);
        double alpha = (om < 1e-28) ? 1.0 : atan(sqrt(om / lam)) / sqrt(om);
        sdA[lane] = (float)(alpha / sqrt(lam));
    }
    __syncwarp();
    // Ts into M (bounded)
    for (int i = lane; i < 256; i += 32)
        M[(i >> 4) * S17 + (i & 15)] = T1f[i] * sdA[i & 15];
    __syncwarp();
    // G = Ts V^T into W slot (W dead)
    for (int i = lane; i < 256; i += 32) {
        int r = i >> 4, cc = i & 15;
        float acc = 0.f;
        #pragma unroll
        for (int x = 0; x < 16; ++x) acc += M[r * S17 + x] * V[cc * S17 + x];
        W[r * S17 + cc] = acc;
    }
    __syncwarp();
    // x_log = Z G -> gXlog
    float4* dst4 = (float4*)(gXlog + (size_t)bc * 1024);
    for (int i4 = lane; i4 < 256; i4 += 32) {
        int r = i4 >> 2, cb = (i4 & 3) * 4;
        float a0 = 0.f, a1 = 0.f, a2 = 0.f, a3 = 0.f;
        #pragma unroll
        for (int x = 0; x < 16; ++x) {
            float z = Z[r * 16 + x];
            a0 += z * W[x * S17 + cb];
            a1 += z * W[x * S17 + cb + 1];
            a2 += z * W[x * S17 + cb + 2];
            a3 += z * W[x * S17 + cb + 3];
        }
        dst4[i4] = make_float4(a0, a1, a2, a3);
    }
}

// K2 (grid=Csz+1): blocks 0..127 per-channel mean/Bm/GinvC; block 128 bias GinvB.
__global__ void k2_mean(const float* __restrict__ X, float* __restrict__ meanOut,
                        const float* __restrict__ bias) {
    __shared__ double Dm[1024], U0[1024], meanS[1024], Cm[768];
    __shared__ double W[256], V[256], M1[256], M2[256], aug[512];
    __shared__ double g[32], cs[16], fs[18];
    __shared__ int piv;
    const int c = blockIdx.x;
    const int t = threadIdx.x;
    if (c == Csz) {
        for (int i = t; i < 768; i += TB) Cm[i] = (double)bias[i];
        __syncthreads();
        gram16d(Cm, W, 48);
        for (int i = t; i < 256; i += TB) {
            int r = i >> 4, cc = i & 15;
            W[i] = 0.25 * W[i] + ((r == cc) ? 1.0 : 0.0);
        }
        __syncthreads();
        invert16d(W, aug, M1, fs, &piv);
        for (int i = t; i < 256; i += TB) gGinvBF[i] = (float)M1[i];
        return;
    }
    const float4* gX4 = (const float4*)gXlog;
    for (int i4 = t; i4 < 256; i4 += TB) {
        float a0 = 0.f, a1 = 0.f, a2 = 0.f, a3 = 0.f;
        #pragma unroll 4
        for (int b = 0; b < Bsz; ++b) {
            float4 v = gX4[((size_t)b * Csz + c) * 256 + i4];
            a0 += v.x; a1 += v.y; a2 += v.z; a3 += v.w;
        }
        const double inv = 1.0 / (double)Bsz;
        int i = i4 * 4;
        Dm[i] = (double)a0 * inv; Dm[i + 1] = (double)a1 * inv;
        Dm[i + 2] = (double)a2 * inv; Dm[i + 3] = (double)a3 * inv;
    }
    for (int i = t; i < 1024; i += TB)
        U0[i] = (double)X[(size_t)c * 1024 + i];
    __syncthreads();
    gram16d(Dm, W, 64);
    jacobi16d(W, V, cs);
    if (t < 16) {
        double S = sqrt(fmax(W[t * 17], 0.0));
        g[t] = cos(S);
        g[16 + t] = (S > 1e-100) ? sin(S) / S : 1.0;
    }
    __syncthreads();
    vdvtd(V, g, M1);
    vdvtd(V, g + 16, M2);
    for (int i = t; i < 1024; i += TB) {
        int r = i >> 4, cc = i & 15;
        double acc = 0.0;
        #pragma unroll
        for (int x = 0; x < 16; ++x)
            acc += U0[r * 16 + x] * M1[x * 16 + cc] + Dm[r * 16 + x] * M2[x * 16 + cc];
        meanS[i] = acc;
        meanOut[c * 1024 + i] = (float)acc;
    }
    __syncthreads();
    invert16d(meanS, aug, M1, fs, &piv);
    matmul16d(meanS + 256, M1, Cm, 48);
    gram16d(Cm, W, 48);
    jacobi16d(W, V, cs);
    if (t < 16) {
        double S = sqrt(fmax(W[t * 17], 0.0));
        g[t] = (S > 1e-100) ? atan(S) / S : 1.0;
    }
    __syncthreads();
    vdvtd(V, g, M2);
    matmul16d(Cm, M2, Dm, 48);
    for (int i = t; i < 768; i += TB) gBmF[c * 768 + i] = (float)Dm[i];
    __syncthreads();
    gram16d(Dm, W, 48);
    for (int i = t; i < 256; i += TB) {
        int r = i >> 4, cc = i & 15;
        W[i] = 0.25 * W[i] + ((r == cc) ? 1.0 : 0.0);
    }
    __syncthreads();
    invert16d(W, aug, M1, fs, &piv);
    for (int i = t; i < 256; i += TB) gGinvCF[c * 256 + i] = (float)M1[i];
}

// K3 (warp-per-instance): theta^2 sum -> gTheta[bc]
__global__ void __launch_bounds__(TB) k3_theta(const float* __restrict__ X,
                                               const float* __restrict__ meanIn) {
    __shared__ alignas(16) float Mn[WPB][1024];
    __shared__ alignas(16) float Xb[WPB][1024];
    __shared__ float Mm[WPB][272];
    const int w = threadIdx.x >> 5, lane = threadIdx.x & 31;
    const int bc = blockIdx.x * WPB + w;
    const int c = bc & (Csz - 1);
    float* A = Mn[w];
    float* Xl = Xb[w];
    float* M = Mm[w];
    float* W = Mn[w];              // overlay (mean dead after M computed)
    const float4* Xp4 = (const float4*)(X + (size_t)bc * 1024);
    const float4* Mp4 = (const float4*)(meanIn + (size_t)c * 1024);
    float4* A4 = (float4*)A;
    float4* Xl4 = (float4*)Xl;
    for (int i = lane; i < 256; i += 32) { A4[i] = Mp4[i]; Xl4[i] = Xp4[i]; }
    __syncwarp();
    for (int i = lane; i < 256; i += 32) {
        int r = i >> 4, cc = i & 15;
        float acc = 0.f;
        for (int x = 0; x < 64; ++x) acc += A[x * 16 + r] * Xl[x * 16 + cc];
        M[r * S17 + cc] = acc;
    }
    __syncwarp();
    for (int i = lane; i < 256; i += 32) {
        int r = i >> 4, cc = i & 15;
        float acc = 0.f;
        #pragma unroll
        for (int x = 0; x < 16; ++x) acc += M[x * S17 + r] * M[x * S17 + cc];
        W[r * S17 + cc] = acc;
    }
    __syncwarp();
    jacobi_warp(W, (float*)0, lane, SWEEPS_NV, false);
    if (lane == 0) {
        float sum = 0.f;
        for (int j2 = 0; j2 < 16; ++j2) {
            float s = sqrtf(fmaxf(W[j2 * 18], 0.f));
            s = fminf(s, 1.f);
            float th = acosf(s);
            sum += th * th;
        }
        gTheta[bc] = sum;
    }
}

// K4 (grid=Csz): per-channel factor via tree reduction only
__global__ void k4_factor(const float* __restrict__ shiftp) {
    __shared__ float red[TB];
    const int t = threadIdx.x;
    const int c = blockIdx.x;
    red[t] = gTheta[t * Csz + c] + gTheta[(t + TB) * Csz + c];
    __syncthreads();
    for (int s = TB / 2; s > 0; s >>= 1) {
        if (t < s) red[t] += red[t + s];
        __syncthreads();
    }
    if (t == 0) {
        double var = (double)red[0] * (1.0 / (double)Bsz);
        gFactorF[c] = (float)((double)shiftp[0] / sqrt(var + 1e-5));
    }
}

// K5 (warp-per-instance): center -> gyro scale -> bias
__global__ void __launch_bounds__(TB) k5_final(const float* __restrict__ X,
                                               const float* __restrict__ bias,
                                               float* __restrict__ out) {
    __shared__ alignas(16) float Xs[WPB][1024];
    __shared__ alignas(16) float Bmw[WPB][768];   // Bm -> V -> bot -> bias
    __shared__ alignas(16) float bufa[WPB][512];  // Ginv/W -> T1f,Tsf -> M2 / GinvB
    __shared__ alignas(16) float Tt[WPB][256];    // T (A) -> top -> T (C)
    __shared__ float lamK[WPB][16], sdK[WPB][16], gkK[WPB][16];
    const int w = threadIdx.x >> 5, lane = threadIdx.x & 31;
    const int bc = blockIdx.x * WPB + w;
    const int c = bc & (Csz - 1);
    float* Xw = Xs[w];
    float* Bw = Bmw[w];
    float* buf_f = bufa[w];
    float* T = Tt[w];
    {
        const float4* Xp4 = (const float4*)(X + (size_t)bc * 1024);
        const float4* Bm4 = (const float4*)(gBmF + (size_t)c * 768);
        const float4* Gi4 = (const float4*)(gGinvCF + (size_t)c * 256);
        float4* Xw4 = (float4*)Xw;
        float4* Bw4 = (float4*)Bw;
        float4* bf4 = (float4*)buf_f;
        for (int i = lane; i < 256; i += 32) Xw4[i] = Xp4[i];
        for (int i = lane; i < 192; i += 32) Bw4[i] = Bm4[i];
        for (int i = lane; i < 64; i += 32) bf4[i] = Gi4[i];
    }
    __syncwarp();
    // --- Step A: centering Cayley ---
    for (int i = lane; i < 256; i += 32) {
        int r = i >> 4, cc = i & 15;
        float acc = Xw[i];
        for (int k = 0; k < 48; ++k)
            acc += 0.5f * Bw[k * 16 + r] * Xw[256 + k * 16 + cc];
        T[i] = acc;
    }
    __syncwarp();
    {
        float yreg[8];
        #pragma unroll
        for (int ii = 0; ii < 8; ++ii) {
            int i = lane + 32 * ii, r = i >> 4, cc = i & 15;
            float acc = 0.f;
            #pragma unroll
            for (int x = 0; x < 16; ++x) acc += buf_f[r * 16 + x] * T[x * 16 + cc];
            yreg[ii] = acc;
        }
        __syncwarp();
        #pragma unroll
        for (int ii = 0; ii < 8; ++ii) T[lane + 32 * ii] = yreg[ii];
    }
    __syncwarp();
    for (int i = lane; i < 1024; i += 32) {
        if (i < 256) Xw[i] = 2.f * T[i] - Xw[i];
        else {
            int r = (i - 256) >> 4, cc = i & 15;
            float acc = Xw[i];
            #pragma unroll
            for (int x = 0; x < 16; ++x) acc -= Bw[r * 16 + x] * T[x * 16 + cc];
            Xw[i] = acc;                       // last use of Bm
        }
    }
    __syncwarp();
    // --- Step B: gyro scaling via K = Xu Xu^T ---
    float* W = buf_f;                          // Ginv dead
    float* V = Bw;                             // Bm dead; V stride-17 in Bmw[0..287]
    for (int i = lane; i < 256; i += 32) {
        int r = i >> 4, cc = i & 15;
        float acc = 0.f;
        #pragma unroll
        for (int x = 0; x < 16; ++x) acc += Xw[r * 16 + x] * Xw[cc * 16 + x];
        W[r * S17 + cc] = acc;
    }
    for (int i = lane; i < 288; i += 32) V[i] = 0.f;
    __syncwarp();
    if (lane < 16) V[lane * S17 + lane] = 1.f;
    jacobi_warp(W, V, lane, SWEEPS_W, true);
    // ---- compensated fp32 T1 (W dead) ----
    float* T1f = buf_f;          // 256
    for (int i = lane; i < 256; i += 32) {
        int r = i >> 4, cc = i & 15;
        float s = 0.f, comp = 0.f;
        #pragma unroll
        for (int x = 0; x < 16; ++x) {
            float a = Xw[x * 16 + r], b = V[x * S17 + cc];
            float p = __fmul_rn(a, b);
            float e = __fmaf_rn(a, b, -p);
            float y = p - comp;
            float t2 = s + y;
            comp = ((t2 - s) - y) - e;
            s = t2;
        }
        T1f[i] = s - comp;
    }
    __syncwarp();
    if (lane < 16) {
        float acc = 0.f;
        #pragma unroll
        for (int r = 0; r < 16; ++r) { float v = T1f[r * 16 + lane]; acc = __fmaf_rn(v, v, acc); }
        lamK[w][lane] = fmaxf(acc, 1e-30f);
    }
    __syncwarp();
    float fct = gFactorF[c];
    if (lane < 16) {
        double lam = (double)lamK[w][lane];
        double om = fmax(1.0 - lam, 0.0);
        double beta, cth;
        if (om < 1e-28) { beta = (double)fct; cth = 1.0; }
        else {
            double th = (double)fct * atan(sqrt(om / lam));
            beta = sin(th) / sqrt(om);
            cth = cos(th);
        }
        sdK[w][lane] = (float)(beta / sqrt(lam));
        gkK[w][lane] = (float)cth;
    }
    __syncwarp();
    float* Tsf = buf_f + 256;
    for (int i = lane; i < 256; i += 32) Tsf[i] = T1f[i] * sdK[w][i & 15];
    __syncwarp();
    // M2 = Ts V^T and top = V cos V^T, staged; commit M2 -> buf_f[0..255], top -> T
    {
        float m2reg[8], topreg[8];
        #pragma unroll
        for (int ii = 0; ii < 8; ++ii) {
            int i = lane + 32 * ii, r = i >> 4, cc = i & 15;
            float accm = 0.f, acct = 0.f;
            #pragma unroll
            for (int x = 0; x < 16; ++x) {
                accm += Tsf[r * 16 + x] * V[cc * S17 + x];
                acct += V[r * S17 + x] * gkK[w][x] * V[cc * S17 + x];
            }
            m2reg[ii] = accm;
            topreg[ii] = acct;
        }
        __syncwarp();
        #pragma unroll
        for (int ii = 0; ii < 8; ++ii) {
            buf_f[lane + 32 * ii] = m2reg[ii];   // M2
            T[lane + 32 * ii] = topreg[ii];      // top
        }
    }
    __syncwarp();
    // bot = Xl M2 into Bw (V dead)
    for (int i = lane; i < 768; i += 32) {
        int r = i >> 4, cc = i & 15;
        float acc = 0.f;
        #pragma unroll
        for (int x = 0; x < 16; ++x) acc += Xw[256 + r * 16 + x] * buf_f[x * 16 + cc];
        Bw[i] = acc;
    }
    __syncwarp();
    // commit: Xu=top, Xl=bot
    {
        float4* Xw4 = (float4*)Xw;
        float4* T4 = (float4*)T;
        float4* Bw4 = (float4*)Bw;
        for (int i = lane; i < 64; i += 32) Xw4[i] = T4[i];
        for (int i = lane; i < 192; i += 32) Xw4[64 + i] = Bw4[i];
    }
    __syncwarp();
    // --- Step C: bias Cayley ---
    {
        const float4* b4 = (const float4*)bias;
        const float4* g4 = (const float4*)gGinvBF;
        float4* Bw4 = (float4*)Bw;
        float4* bf4 = (float4*)buf_f;
        for (int i = lane; i < 192; i += 32) Bw4[i] = b4[i];
        for (int i = lane; i < 64; i += 32) bf4[i] = g4[i];
    }
    __syncwarp();
    for (int i = lane; i < 256; i += 32) {
        int r = i >> 4, cc = i & 15;
        float acc = Xw[i];
        for (int k = 0; k < 48; ++k)
            acc -= 0.5f * Bw[k * 16 + r] * Xw[256 + k * 16 + cc];
        T[i] = acc;
    }
    __syncwarp();
    {
        float yreg[8];
        #pragma unroll
        for (int ii = 0; ii < 8; ++ii) {
            int i = lane + 32 * ii, r = i >> 4, cc = i & 15;
            float acc = 0.f;
            #pragma unroll
            for (int x = 0; x < 16; ++x) acc += buf_f[r * 16 + x] * T[x * 16 + cc];
            yreg[ii] = acc;
        }
        __syncwarp();
        #pragma unroll
        for (int ii = 0; ii < 8; ++ii) T[lane + 32 * ii] = yreg[ii];
    }
    __syncwarp();
    float4* dst4 = (float4*)(out + (size_t)bc * 1024);
    for (int i4 = lane; i4 < 64; i4 += 32) {
        float4 t4 = ((float4*)T)[i4];
        float4 x4 = ((float4*)Xw)[i4];
        dst4[i4] = make_float4(2.f * t4.x - x4.x, 2.f * t4.y - x4.y,
                               2.f * t4.z - x4.z, 2.f * t4.w - x4.w);
    }
    for (int i4 = lane; i4 < 192; i4 += 32) {
        int r = i4 >> 2, cb = (i4 & 3) * 4;
        float a0 = Xw[256 + r * 16 + cb];
        float a1 = Xw[256 + r * 16 + cb + 1];
        float a2 = Xw[256 + r * 16 + cb + 2];
        float a3 = Xw[256 + r * 16 + cb + 3];
        #pragma unroll
        for (int x = 0; x < 16; ++x) {
            float bv = Bw[r * 16 + x];
            a0 += bv * T[x * 16 + cb];
            a1 += bv * T[x * 16 + cb + 1];
            a2 += bv * T[x * 16 + cb + 2];
            a3 += bv * T[x * 16 + cb + 3];
        }
        dst4[64 + i4] = make_float4(a0, a1, a2, a3);
    }
}

// ---------------- launch ----------------
extern "C" void kernel_launch(void* const* d_in, const int* in_sizes, int n_in,
                              void* d_out, int out_size) {
    const float* X = (const float*)d_in[0];
    const float* bias = (const float*)d_in[1];
    const float* shift = (const float*)d_in[2];
    float* out = (float*)d_out;
    float* meanOut = out + (size_t)Bsz * Csz * Nsz * Psz;

    const int nInst = Bsz * Csz;
    k1_logmap<<<nInst / WPB, TB>>>(X);
    k2_mean<<<Csz + 1, TB>>>(X, meanOut, bias);
    k3_theta<<<nInst / WPB, TB>>>(X, meanOut);
    k4_factor<<<Csz, TB>>>(shift);
    k5_final<<<nInst / WPB, TB>>>(X, bias, out);
}